// round 3
// baseline (speedup 1.0000x reference)
#include <cuda_runtime.h>
#include <math.h>
#include <stdint.h>

#define DIMSZ 1024
#define BATCH 2
#define SEQ 1024
#define HEADS 16
#define DHEAD 64
#define HIDDEN 4096
#define MROWS (BATCH*SEQ)          /* 2048 */
#define BND (MROWS*DIMSZ)          /* 2097152 */

// ---------------- scratch (__device__ globals; no allocation allowed) ----------------
__device__ float g_Qr[BND], g_Qi[BND];
__device__ float g_Kr[BND], g_Ki[BND];
__device__ float g_Vr[BND], g_Vi[BND];
__device__ float g_S[(size_t)BATCH*HEADS*SEQ*SEQ];   // 32 * 1024 * 1024
__device__ float g_OFr[BND], g_OFi[BND];
__device__ float g_x1r[BND], g_x1i[BND];
__device__ float g_x2r[BND], g_x2i[BND];
__device__ float g_hr[MROWS*HIDDEN], g_hi[MROWS*HIDDEN];
__device__ float g_Mx[DIMSZ*DIMSZ], g_P2[DIMSZ*DIMSZ];
__device__ float g_T1[DIMSZ*DIMSZ], g_T2[DIMSZ*DIMSZ];
__device__ float g_Ucos[DIMSZ*DIMSZ], g_UsinN[DIMSZ*DIMSZ];

__device__ __forceinline__ float gelu_f(float x) {
    return 0.5f * x * (1.0f + erff(x * 0.70710678118654752440f));
}

// ---------------- complex GEMM: C = A @ W^T (+bias)(+gelu)(+residual) ----------------
// A: [M,K] (Ar,Ai), W: [Nn,K] (Wr,Wi) row-major; C: [M,Nn]
// flags bit0: add residual (Rr,Ri same shape as C); bit1: gelu epilogue
__global__ __launch_bounds__(256) void cgemm_kernel(
    const float* __restrict__ Ar, const float* __restrict__ Ai,
    const float* __restrict__ Wr, const float* __restrict__ Wi,
    const float* __restrict__ br, const float* __restrict__ bi,
    const float* __restrict__ Rr, const float* __restrict__ Ri,
    float* __restrict__ Cr, float* __restrict__ Ci,
    int Mq, int Nn, int K, int flags)
{
    __shared__ float As_r[16][68], As_i[16][68], Ws_r[16][68], Ws_i[16][68];
    const int bm = blockIdx.y * 64, bn = blockIdx.x * 64;
    const int tid = threadIdx.x;
    const int tx = tid & 15, ty = tid >> 4;
    float cr[4][4] = {{0.f}}, ci[4][4] = {{0.f}};

    for (int k0 = 0; k0 < K; k0 += 16) {
        #pragma unroll
        for (int i = 0; i < 4; i++) {
            int idx = tid + i * 256;
            int m = idx >> 4, kk = idx & 15;
            size_t ao = (size_t)(bm + m) * K + k0 + kk;
            size_t wo = (size_t)(bn + m) * K + k0 + kk;
            As_r[kk][m] = Ar[ao]; As_i[kk][m] = Ai[ao];
            Ws_r[kk][m] = Wr[wo]; Ws_i[kk][m] = Wi[wo];
        }
        __syncthreads();
        #pragma unroll
        for (int kk = 0; kk < 16; kk++) {
            float4 a_r = *(const float4*)&As_r[kk][ty * 4];
            float4 a_i = *(const float4*)&As_i[kk][ty * 4];
            float4 w_r = *(const float4*)&Ws_r[kk][tx * 4];
            float4 w_i = *(const float4*)&Ws_i[kk][tx * 4];
            float ar[4] = {a_r.x, a_r.y, a_r.z, a_r.w};
            float ai2[4] = {a_i.x, a_i.y, a_i.z, a_i.w};
            float wr[4] = {w_r.x, w_r.y, w_r.z, w_r.w};
            float wi2[4] = {w_i.x, w_i.y, w_i.z, w_i.w};
            #pragma unroll
            for (int i = 0; i < 4; i++)
                #pragma unroll
                for (int j = 0; j < 4; j++) {
                    cr[i][j] += ar[i] * wr[j];
                    cr[i][j] -= ai2[i] * wi2[j];
                    ci[i][j] += ar[i] * wi2[j];
                    ci[i][j] += ai2[i] * wr[j];
                }
        }
        __syncthreads();
    }
    #pragma unroll
    for (int i = 0; i < 4; i++)
        #pragma unroll
        for (int j = 0; j < 4; j++) {
            int m = bm + ty * 4 + i, n = bn + tx * 4 + j;
            float vr = cr[i][j], vi = ci[i][j];
            if (br) { vr += br[n]; vi += bi[n]; }
            if (flags & 2) { vr = gelu_f(vr); vi = gelu_f(vi); }
            size_t o = (size_t)m * Nn + n;
            if (flags & 1) { vr += Rr[o]; vi += Ri[o]; }
            Cr[o] = vr; Ci[o] = vi;
        }
}

// ---------------- real GEMM (1024^3): C = scl*(A @ B) + alpha*I ----------------
__global__ __launch_bounds__(256) void rgemm_kernel(
    const float* __restrict__ A, const float* __restrict__ Bm,
    float* __restrict__ C, float scl, float alpha)
{
    __shared__ float As[16][68], Bs[16][68];
    const int bm = blockIdx.y * 64, bn = blockIdx.x * 64;
    const int tid = threadIdx.x;
    const int tx = tid & 15, ty = tid >> 4;
    float acc[4][4] = {{0.f}};
    for (int k0 = 0; k0 < DIMSZ; k0 += 16) {
        #pragma unroll
        for (int i = 0; i < 4; i++) {
            int idx = tid + i * 256;
            int m = idx >> 4, kk = idx & 15;
            As[kk][m] = A[(size_t)(bm + m) * DIMSZ + k0 + kk];
            int n = idx & 63, k2 = idx >> 6;
            Bs[k2][n] = Bm[(size_t)(k0 + k2) * DIMSZ + bn + n];
        }
        __syncthreads();
        #pragma unroll
        for (int kk = 0; kk < 16; kk++) {
            float4 a4 = *(const float4*)&As[kk][ty * 4];
            float4 b4 = *(const float4*)&Bs[kk][tx * 4];
            float a[4] = {a4.x, a4.y, a4.z, a4.w};
            float b[4] = {b4.x, b4.y, b4.z, b4.w};
            #pragma unroll
            for (int i = 0; i < 4; i++)
                #pragma unroll
                for (int j = 0; j < 4; j++)
                    acc[i][j] += a[i] * b[j];
        }
        __syncthreads();
    }
    #pragma unroll
    for (int i = 0; i < 4; i++)
        #pragma unroll
        for (int j = 0; j < 4; j++) {
            int m = bm + ty * 4 + i, n = bn + tx * 4 + j;
            C[(size_t)m * DIMSZ + n] = scl * acc[i][j] + ((m == n) ? alpha : 0.f);
        }
}

// ---------------- FFT along seq axis: data [B, N, C], transform each (b,c) column ----
// 4 channels per block; inv=0: fft (sign -1, scale 1); inv=1: ifft (sign +1, scale 1/N)
__global__ __launch_bounds__(256) void fft_kernel(float* __restrict__ re, float* __restrict__ im,
                                                  int inv, float scale)
{
    __shared__ float sr[SEQ * 4], si[SEQ * 4];
    const int c0 = blockIdx.x * 4;
    const int b = blockIdx.y;
    const size_t base = (size_t)b * SEQ * DIMSZ;
    const int tid = threadIdx.x;
    const float sgn = inv ? 1.0f : -1.0f;

    for (int i = tid; i < SEQ * 4; i += 256) {
        int n = i >> 2, c = i & 3;
        int rn = __brev((unsigned)n) >> 22;
        size_t g = base + (size_t)n * DIMSZ + c0 + c;
        sr[rn * 4 + c] = re[g];
        si[rn * 4 + c] = im[g];
    }
    __syncthreads();

    for (int s = 1; s <= 10; s++) {
        int half = 1 << (s - 1);
        float angstep = sgn * 6.283185307179586f / (float)(1 << s);
        for (int i = tid; i < 2048; i += 256) {
            int j = i >> 2, c = i & 3;
            int k = j & (half - 1);
            int grp = j >> (s - 1);
            int i0 = ((grp << s) + k) * 4 + c;
            int i1 = i0 + half * 4;
            float cw, sw;
            sincosf(angstep * (float)k, &sw, &cw);
            float ur = sr[i0], ui = si[i0];
            float vr = sr[i1], vi = si[i1];
            float tr = vr * cw - vi * sw;
            float ti = vr * sw + vi * cw;
            sr[i0] = ur + tr; si[i0] = ui + ti;
            sr[i1] = ur - tr; si[i1] = ui - ti;
        }
        __syncthreads();
    }

    for (int i = tid; i < SEQ * 4; i += 256) {
        int n = i >> 2, c = i & 3;
        size_t g = base + (size_t)n * DIMSZ + c0 + c;
        re[g] = sr[n * 4 + c] * scale;
        im[g] = si[n * 4 + c] * scale;
    }
}

// ---------------- scores: S[b,h,i,j] = scale * (Qr.Kr + Qi.Ki) over dh=64 -----------
__global__ __launch_bounds__(256) void qk_kernel(
    const float* __restrict__ Qr, const float* __restrict__ Qi,
    const float* __restrict__ Kr, const float* __restrict__ Ki,
    float* __restrict__ S)
{
    const int bh = blockIdx.z;
    const int b = bh >> 4, h = bh & 15;
    const size_t xb = (size_t)b * SEQ * DIMSZ + h * DHEAD;
    const float* qr = Qr + xb; const float* qi = Qi + xb;
    const float* kr = Kr + xb; const float* ki = Ki + xb;
    float* s = S + (size_t)bh * SEQ * SEQ;
    const int bi_ = blockIdx.y * 64, bj = blockIdx.x * 64;
    const int tid = threadIdx.x;
    const int tx = tid & 15, ty = tid >> 4;
    __shared__ float Qsr[16][68], Qsi[16][68], Ksr[16][68], Ksi[16][68];
    float acc[4][4] = {{0.f}};
    for (int k0 = 0; k0 < DHEAD; k0 += 16) {
        #pragma unroll
        for (int i = 0; i < 4; i++) {
            int idx = tid + i * 256;
            int m = idx >> 4, kk = idx & 15;
            Qsr[kk][m] = qr[(size_t)(bi_ + m) * DIMSZ + k0 + kk];
            Qsi[kk][m] = qi[(size_t)(bi_ + m) * DIMSZ + k0 + kk];
            Ksr[kk][m] = kr[(size_t)(bj + m) * DIMSZ + k0 + kk];
            Ksi[kk][m] = ki[(size_t)(bj + m) * DIMSZ + k0 + kk];
        }
        __syncthreads();
        #pragma unroll
        for (int kk = 0; kk < 16; kk++) {
            float4 q_r = *(const float4*)&Qsr[kk][ty * 4];
            float4 q_i = *(const float4*)&Qsi[kk][ty * 4];
            float4 k_r = *(const float4*)&Ksr[kk][tx * 4];
            float4 k_i = *(const float4*)&Ksi[kk][tx * 4];
            float qrv[4] = {q_r.x, q_r.y, q_r.z, q_r.w};
            float qiv[4] = {q_i.x, q_i.y, q_i.z, q_i.w};
            float krv[4] = {k_r.x, k_r.y, k_r.z, k_r.w};
            float kiv[4] = {k_i.x, k_i.y, k_i.z, k_i.w};
            #pragma unroll
            for (int i = 0; i < 4; i++)
                #pragma unroll
                for (int j = 0; j < 4; j++) {
                    acc[i][j] += qrv[i] * krv[j];
                    acc[i][j] += qiv[i] * kiv[j];
                }
        }
        __syncthreads();
    }
    #pragma unroll
    for (int i = 0; i < 4; i++)
        #pragma unroll
        for (int j = 0; j < 4; j++)
            s[(size_t)(bi_ + ty * 4 + i) * SEQ + bj + tx * 4 + j] = acc[i][j] * 0.125f;
}

// ---------------- softmax over last dim (1024) ----------------
__global__ __launch_bounds__(256) void softmax_kernel(float* __restrict__ S)
{
    float* row = S + (size_t)blockIdx.x * SEQ;
    const int t = threadIdx.x;
    __shared__ float red[256];
    float4 v = *(float4*)&row[t * 4];
    float m = fmaxf(fmaxf(v.x, v.y), fmaxf(v.z, v.w));
    red[t] = m; __syncthreads();
    for (int s = 128; s > 0; s >>= 1) {
        if (t < s) red[t] = fmaxf(red[t], red[t + s]);
        __syncthreads();
    }
    m = red[0]; __syncthreads();
    v.x = expf(v.x - m); v.y = expf(v.y - m);
    v.z = expf(v.z - m); v.w = expf(v.w - m);
    float sum = v.x + v.y + v.z + v.w;
    red[t] = sum; __syncthreads();
    for (int s = 128; s > 0; s >>= 1) {
        if (t < s) red[t] += red[t + s];
        __syncthreads();
    }
    float inv = 1.0f / red[0];
    v.x *= inv; v.y *= inv; v.z *= inv; v.w *= inv;
    *(float4*)&row[t * 4] = v;
}

// ---------------- out_f = attn @ Vf (attn real, Vf complex) ----------------
__global__ __launch_bounds__(256) void av_kernel(
    const float* __restrict__ S, const float* __restrict__ Vr, const float* __restrict__ Vi,
    float* __restrict__ Or, float* __restrict__ Oi)
{
    const int bh = blockIdx.z;
    const int b = bh >> 4, h = bh & 15;
    const float* a = S + (size_t)bh * SEQ * SEQ;
    const size_t vb = (size_t)b * SEQ * DIMSZ + h * DHEAD;
    const float* vr = Vr + vb; const float* vi = Vi + vb;
    float* outr = Or + vb; float* outi = Oi + vb;
    const int bi_ = blockIdx.x * 64;
    const int tid = threadIdx.x;
    const int tx = tid & 15, ty = tid >> 4;
    __shared__ float As[16][68], Vsr[16][68], Vsi[16][68];
    float accr[4][4] = {{0.f}}, acci[4][4] = {{0.f}};
    for (int k0 = 0; k0 < SEQ; k0 += 16) {
        #pragma unroll
        for (int i = 0; i < 4; i++) {
            int idx = tid + i * 256;
            int m = idx >> 4, kk = idx & 15;
            As[kk][m] = a[(size_t)(bi_ + m) * SEQ + k0 + kk];
            int n = idx & 63, k2 = idx >> 6;
            Vsr[k2][n] = vr[(size_t)(k0 + k2) * DIMSZ + n];
            Vsi[k2][n] = vi[(size_t)(k0 + k2) * DIMSZ + n];
        }
        __syncthreads();
        #pragma unroll
        for (int kk = 0; kk < 16; kk++) {
            float4 a4 = *(const float4*)&As[kk][ty * 4];
            float4 v_r = *(const float4*)&Vsr[kk][tx * 4];
            float4 v_i = *(const float4*)&Vsi[kk][tx * 4];
            float av[4] = {a4.x, a4.y, a4.z, a4.w};
            float vrv[4] = {v_r.x, v_r.y, v_r.z, v_r.w};
            float viv[4] = {v_i.x, v_i.y, v_i.z, v_i.w};
            #pragma unroll
            for (int i = 0; i < 4; i++)
                #pragma unroll
                for (int j = 0; j < 4; j++) {
                    accr[i][j] += av[i] * vrv[j];
                    acci[i][j] += av[i] * viv[j];
                }
        }
        __syncthreads();
    }
    #pragma unroll
    for (int i = 0; i < 4; i++)
        #pragma unroll
        for (int j = 0; j < 4; j++) {
            size_t o = (size_t)(bi_ + ty * 4 + i) * DIMSZ + tx * 4 + j;
            outr[o] = accr[i][j];
            outi[o] = acci[i][j];
        }
}

// ---------------- small elementwise kernels ----------------
__global__ __launch_bounds__(256) void scaleH_kernel(const float* __restrict__ H,
                                                     const float* __restrict__ dt,
                                                     float* __restrict__ M)
{
    int i = blockIdx.x * 256 + threadIdx.x;
    M[i] = H[i] * dt[0];
}

__global__ __launch_bounds__(256) void axpbI_kernel(const float* __restrict__ P,
                                                    float a, float b, float* __restrict__ T)
{
    int i = blockIdx.x * 256 + threadIdx.x;
    float v = a * P[i];
    int r = i >> 10, c = i & 1023;
    if (r == c) v += b;
    T[i] = v;
}

// ---------------- host launch ----------------
static float* symaddr(const void* sym)
{
    void* p = nullptr;
    cudaGetSymbolAddress(&p, sym);
    return (float*)p;
}

extern "C" void kernel_launch(void* const* d_in, const int* in_sizes, int n_in,
                              void* d_out, int out_size)
{
    const float* xr = (const float*)d_in[0];
    const float* xi = (const float*)d_in[1];
    const float* Wr_q = (const float*)d_in[2];  const float* Wi_q = (const float*)d_in[3];
    const float* br_q = (const float*)d_in[4];  const float* bi_q = (const float*)d_in[5];
    const float* Wr_k = (const float*)d_in[6];  const float* Wi_k = (const float*)d_in[7];
    const float* br_k = (const float*)d_in[8];  const float* bi_k = (const float*)d_in[9];
    const float* Wr_v = (const float*)d_in[10]; const float* Wi_v = (const float*)d_in[11];
    const float* br_v = (const float*)d_in[12]; const float* bi_v = (const float*)d_in[13];
    const float* Wr_o = (const float*)d_in[14]; const float* Wi_o = (const float*)d_in[15];
    const float* br_o = (const float*)d_in[16]; const float* bi_o = (const float*)d_in[17];
    const float* Wr_f1 = (const float*)d_in[18]; const float* Wi_f1 = (const float*)d_in[19];
    const float* br_f1 = (const float*)d_in[20]; const float* bi_f1 = (const float*)d_in[21];
    const float* Wr_f2 = (const float*)d_in[22]; const float* Wi_f2 = (const float*)d_in[23];
    const float* br_f2 = (const float*)d_in[24]; const float* bi_f2 = (const float*)d_in[25];
    const float* Hm = (const float*)d_in[26];
    const float* dt = (const float*)d_in[27];

    float* Qr = symaddr(g_Qr);   float* Qi = symaddr(g_Qi);
    float* Kr = symaddr(g_Kr);   float* Ki = symaddr(g_Ki);
    float* Vr = symaddr(g_Vr);   float* Vi = symaddr(g_Vi);
    float* Sb = symaddr(g_S);
    float* OFr = symaddr(g_OFr); float* OFi = symaddr(g_OFi);
    float* x1r = symaddr(g_x1r); float* x1i = symaddr(g_x1i);
    float* x2r = symaddr(g_x2r); float* x2i = symaddr(g_x2i);
    float* hr = symaddr(g_hr);   float* hi = symaddr(g_hi);
    float* Mx = symaddr(g_Mx);   float* P2 = symaddr(g_P2);
    float* T1 = symaddr(g_T1);   float* T2 = symaddr(g_T2);
    float* Uc = symaddr(g_Ucos); float* Us = symaddr(g_UsinN);

    dim3 blk(256);
    dim3 gP(DIMSZ / 64, MROWS / 64);      // (16, 32)
    dim3 gF(DIMSZ / 4, BATCH);            // (256, 2)
    dim3 gS(SEQ / 64, SEQ / 64, BATCH * HEADS);
    dim3 gA(SEQ / 64, 1, BATCH * HEADS);
    dim3 gR(DIMSZ / 64, DIMSZ / 64);      // (16, 16)
    dim3 gF1(HIDDEN / 64, MROWS / 64);    // (64, 32)

    // --- QKV projections ---
    cgemm_kernel<<<gP, blk>>>(xr, xi, Wr_q, Wi_q, br_q, bi_q, nullptr, nullptr,
                              Qr, Qi, MROWS, DIMSZ, DIMSZ, 0);
    cgemm_kernel<<<gP, blk>>>(xr, xi, Wr_k, Wi_k, br_k, bi_k, nullptr, nullptr,
                              Kr, Ki, MROWS, DIMSZ, DIMSZ, 0);
    cgemm_kernel<<<gP, blk>>>(xr, xi, Wr_v, Wi_v, br_v, bi_v, nullptr, nullptr,
                              Vr, Vi, MROWS, DIMSZ, DIMSZ, 0);

    // --- FFTs along sequence ---
    fft_kernel<<<gF, blk>>>(Qr, Qi, 0, 1.0f);
    fft_kernel<<<gF, blk>>>(Kr, Ki, 0, 1.0f);
    fft_kernel<<<gF, blk>>>(Vr, Vi, 0, 1.0f);

    // --- attention ---
    qk_kernel<<<gS, blk>>>(Qr, Qi, Kr, Ki, Sb);
    softmax_kernel<<<BATCH * HEADS * SEQ, blk>>>(Sb);
    av_kernel<<<gA, blk>>>(Sb, Vr, Vi, OFr, OFi);
    fft_kernel<<<gF, blk>>>(OFr, OFi, 1, 1.0f / (float)SEQ);

    // --- O projection + residual ---
    cgemm_kernel<<<gP, blk>>>(OFr, OFi, Wr_o, Wi_o, br_o, bi_o, xr, xi,
                              x1r, x1i, MROWS, DIMSZ, DIMSZ, 1);

    // --- FFN ---
    cgemm_kernel<<<gF1, blk>>>(x1r, x1i, Wr_f1, Wi_f1, br_f1, bi_f1, nullptr, nullptr,
                               hr, hi, MROWS, HIDDEN, DIMSZ, 2);
    cgemm_kernel<<<gP, blk>>>(hr, hi, Wr_f2, Wi_f2, br_f2, bi_f2, x1r, x1i,
                              x2r, x2i, MROWS, DIMSZ, HIDDEN, 1);

    // --- U = expm(-i H dt) = cos(dtH) - i sin(dtH), via Taylor/Horner in P2=(dtH)^2 ---
    scaleH_kernel<<<DIMSZ * DIMSZ / 256, blk>>>(Hm, dt, Mx);
    rgemm_kernel<<<gR, blk>>>(Mx, Mx, P2, 1.0f, 0.0f);
    // cos: ((c3*P2 + c2*I)*P2 + c1*I)*P2 + I, c3=-1/720, c2=1/24, c1=-1/2
    axpbI_kernel<<<DIMSZ * DIMSZ / 256, blk>>>(P2, -1.0f / 720.0f, 1.0f / 24.0f, T1);
    rgemm_kernel<<<gR, blk>>>(T1, P2, T2, 1.0f, -0.5f);
    rgemm_kernel<<<gR, blk>>>(T2, P2, Uc, 1.0f, 1.0f);
    // sin: M * (((s3*P2 + s2*I)*P2 + s1*I)*P2 + I), s3=-1/5040, s2=1/120, s1=-1/6
    axpbI_kernel<<<DIMSZ * DIMSZ / 256, blk>>>(P2, -1.0f / 5040.0f, 1.0f / 120.0f, T1);
    rgemm_kernel<<<gR, blk>>>(T1, P2, T2, 1.0f, -1.0f / 6.0f);
    rgemm_kernel<<<gR, blk>>>(T2, P2, T1, 1.0f, 1.0f);
    rgemm_kernel<<<gR, blk>>>(Mx, T1, Us, -1.0f, 0.0f);   // Us = -sin(dtH)

    // --- final: out = x2 @ U; U symmetric so U == U^T, reuse linear-layer GEMM ---
    float* outR = (float*)d_out;
    float* outI = outR + (size_t)MROWS * DIMSZ;
    cgemm_kernel<<<gP, blk>>>(x2r, x2i, Uc, Us, nullptr, nullptr, nullptr, nullptr,
                              outR, outI, MROWS, DIMSZ, DIMSZ, 0);
}

// round 8
// speedup vs baseline: 1.0039x; 1.0039x over previous
#include <cuda_runtime.h>
#include <math.h>
#include <stdint.h>

#define DIMSZ 1024
#define BATCH 2
#define SEQ 1024
#define HEADS 16
#define DHEAD 64
#define HIDDEN 4096
#define MROWS (BATCH*SEQ)          /* 2048 */
#define BND (MROWS*DIMSZ)          /* 2097152 */

// ---------------- scratch (__device__ globals; no allocation allowed) ----------------
__device__ float g_Qr[BND], g_Qi[BND];
__device__ float g_Kr[BND], g_Ki[BND];
__device__ float g_Vr[BND], g_Vi[BND];
__device__ float g_S[(size_t)BATCH*HEADS*SEQ*SEQ];   // 32 * 1024 * 1024
__device__ float g_OFr[BND], g_OFi[BND];
__device__ float g_x1r[BND], g_x1i[BND];
__device__ float g_x2r[BND], g_x2i[BND];
__device__ float g_hr[MROWS*HIDDEN], g_hi[MROWS*HIDDEN];
__device__ float g_Mx[DIMSZ*DIMSZ], g_P2[DIMSZ*DIMSZ];
__device__ float g_T1[DIMSZ*DIMSZ], g_T2[DIMSZ*DIMSZ];
__device__ float g_Ucos[DIMSZ*DIMSZ], g_UsinN[DIMSZ*DIMSZ];

__device__ __forceinline__ float gelu_f(float x) {
    return 0.5f * x * (1.0f + erff(x * 0.70710678118654752440f));
}

// ---------------- complex GEMM: C = A @ W^T (+bias)(+gelu)(+residual) ----------------
// A: [M,K] (Ar,Ai), W: [Nn,K] (Wr,Wi) row-major; C: [M,Nn]
// flags bit0: add residual (Rr,Ri same shape as C); bit1: gelu epilogue
__global__ __launch_bounds__(256) void cgemm_kernel(
    const float* __restrict__ Ar, const float* __restrict__ Ai,
    const float* __restrict__ Wr, const float* __restrict__ Wi,
    const float* __restrict__ br, const float* __restrict__ bi,
    const float* __restrict__ Rr, const float* __restrict__ Ri,
    float* __restrict__ Cr, float* __restrict__ Ci,
    int Mq, int Nn, int K, int flags)
{
    __shared__ float As_r[16][68], As_i[16][68], Ws_r[16][68], Ws_i[16][68];
    const int bm = blockIdx.y * 64, bn = blockIdx.x * 64;
    const int tid = threadIdx.x;
    const int tx = tid & 15, ty = tid >> 4;
    float cr[4][4] = {{0.f}}, ci[4][4] = {{0.f}};

    for (int k0 = 0; k0 < K; k0 += 16) {
        #pragma unroll
        for (int i = 0; i < 4; i++) {
            int idx = tid + i * 256;
            int m = idx >> 4, kk = idx & 15;
            size_t ao = (size_t)(bm + m) * K + k0 + kk;
            size_t wo = (size_t)(bn + m) * K + k0 + kk;
            As_r[kk][m] = Ar[ao]; As_i[kk][m] = Ai[ao];
            Ws_r[kk][m] = Wr[wo]; Ws_i[kk][m] = Wi[wo];
        }
        __syncthreads();
        #pragma unroll
        for (int kk = 0; kk < 16; kk++) {
            float4 a_r = *(const float4*)&As_r[kk][ty * 4];
            float4 a_i = *(const float4*)&As_i[kk][ty * 4];
            float4 w_r = *(const float4*)&Ws_r[kk][tx * 4];
            float4 w_i = *(const float4*)&Ws_i[kk][tx * 4];
            float ar[4] = {a_r.x, a_r.y, a_r.z, a_r.w};
            float ai2[4] = {a_i.x, a_i.y, a_i.z, a_i.w};
            float wr[4] = {w_r.x, w_r.y, w_r.z, w_r.w};
            float wi2[4] = {w_i.x, w_i.y, w_i.z, w_i.w};
            #pragma unroll
            for (int i = 0; i < 4; i++)
                #pragma unroll
                for (int j = 0; j < 4; j++) {
                    cr[i][j] += ar[i] * wr[j];
                    cr[i][j] -= ai2[i] * wi2[j];
                    ci[i][j] += ar[i] * wi2[j];
                    ci[i][j] += ai2[i] * wr[j];
                }
        }
        __syncthreads();
    }
    #pragma unroll
    for (int i = 0; i < 4; i++)
        #pragma unroll
        for (int j = 0; j < 4; j++) {
            int m = bm + ty * 4 + i, n = bn + tx * 4 + j;
            float vr = cr[i][j], vi = ci[i][j];
            if (br) { vr += br[n]; vi += bi[n]; }
            if (flags & 2) { vr = gelu_f(vr); vi = gelu_f(vi); }
            size_t o = (size_t)m * Nn + n;
            if (flags & 1) { vr += Rr[o]; vi += Ri[o]; }
            Cr[o] = vr; Ci[o] = vi;
        }
}

// ---------------- real GEMM (1024^3): C = scl*(A @ B) + alpha*I ----------------
__global__ __launch_bounds__(256) void rgemm_kernel(
    const float* __restrict__ A, const float* __restrict__ Bm,
    float* __restrict__ C, float scl, float alpha)
{
    __shared__ float As[16][68], Bs[16][68];
    const int bm = blockIdx.y * 64, bn = blockIdx.x * 64;
    const int tid = threadIdx.x;
    const int tx = tid & 15, ty = tid >> 4;
    float acc[4][4] = {{0.f}};
    for (int k0 = 0; k0 < DIMSZ; k0 += 16) {
        #pragma unroll
        for (int i = 0; i < 4; i++) {
            int idx = tid + i * 256;
            int m = idx >> 4, kk = idx & 15;
            As[kk][m] = A[(size_t)(bm + m) * DIMSZ + k0 + kk];
            int n = idx & 63, k2 = idx >> 6;
            Bs[k2][n] = Bm[(size_t)(k0 + k2) * DIMSZ + bn + n];
        }
        __syncthreads();
        #pragma unroll
        for (int kk = 0; kk < 16; kk++) {
            float4 a4 = *(const float4*)&As[kk][ty * 4];
            float4 b4 = *(const float4*)&Bs[kk][tx * 4];
            float a[4] = {a4.x, a4.y, a4.z, a4.w};
            float b[4] = {b4.x, b4.y, b4.z, b4.w};
            #pragma unroll
            for (int i = 0; i < 4; i++)
                #pragma unroll
                for (int j = 0; j < 4; j++)
                    acc[i][j] += a[i] * b[j];
        }
        __syncthreads();
    }
    #pragma unroll
    for (int i = 0; i < 4; i++)
        #pragma unroll
        for (int j = 0; j < 4; j++) {
            int m = bm + ty * 4 + i, n = bn + tx * 4 + j;
            C[(size_t)m * DIMSZ + n] = scl * acc[i][j] + ((m == n) ? alpha : 0.f);
        }
}

// ---------------- FFT along seq axis: data [B, N, C], transform each (b,c) column ----
// 4 channels per block; inv=0: fft (sign -1, scale 1); inv=1: ifft (sign +1, scale 1/N)
__global__ __launch_bounds__(256) void fft_kernel(float* __restrict__ re, float* __restrict__ im,
                                                  int inv, float scale)
{
    __shared__ float sr[SEQ * 4], si[SEQ * 4];
    const int c0 = blockIdx.x * 4;
    const int b = blockIdx.y;
    const size_t base = (size_t)b * SEQ * DIMSZ;
    const int tid = threadIdx.x;
    const float sgn = inv ? 1.0f : -1.0f;

    for (int i = tid; i < SEQ * 4; i += 256) {
        int n = i >> 2, c = i & 3;
        int rn = __brev((unsigned)n) >> 22;
        size_t g = base + (size_t)n * DIMSZ + c0 + c;
        sr[rn * 4 + c] = re[g];
        si[rn * 4 + c] = im[g];
    }
    __syncthreads();

    for (int s = 1; s <= 10; s++) {
        int half = 1 << (s - 1);
        float angstep = sgn * 6.283185307179586f / (float)(1 << s);
        for (int i = tid; i < 2048; i += 256) {
            int j = i >> 2, c = i & 3;
            int k = j & (half - 1);
            int grp = j >> (s - 1);
            int i0 = ((grp << s) + k) * 4 + c;
            int i1 = i0 + half * 4;
            float cw, sw;
            sincosf(angstep * (float)k, &sw, &cw);
            float ur = sr[i0], ui = si[i0];
            float vr = sr[i1], vi = si[i1];
            float tr = vr * cw - vi * sw;
            float ti = vr * sw + vi * cw;
            sr[i0] = ur + tr; si[i0] = ui + ti;
            sr[i1] = ur - tr; si[i1] = ui - ti;
        }
        __syncthreads();
    }

    for (int i = tid; i < SEQ * 4; i += 256) {
        int n = i >> 2, c = i & 3;
        size_t g = base + (size_t)n * DIMSZ + c0 + c;
        re[g] = sr[n * 4 + c] * scale;
        im[g] = si[n * 4 + c] * scale;
    }
}

// ---------------- scores: S[b,h,i,j] = scale * (Qr.Kr + Qi.Ki) over dh=64 -----------
__global__ __launch_bounds__(256) void qk_kernel(
    const float* __restrict__ Qr, const float* __restrict__ Qi,
    const float* __restrict__ Kr, const float* __restrict__ Ki,
    float* __restrict__ S)
{
    const int bh = blockIdx.z;
    const int b = bh >> 4, h = bh & 15;
    const size_t xb = (size_t)b * SEQ * DIMSZ + h * DHEAD;
    const float* qr = Qr + xb; const float* qi = Qi + xb;
    const float* kr = Kr + xb; const float* ki = Ki + xb;
    float* s = S + (size_t)bh * SEQ * SEQ;
    const int bi_ = blockIdx.y * 64, bj = blockIdx.x * 64;
    const int tid = threadIdx.x;
    const int tx = tid & 15, ty = tid >> 4;
    __shared__ float Qsr[16][68], Qsi[16][68], Ksr[16][68], Ksi[16][68];
    float acc[4][4] = {{0.f}};
    for (int k0 = 0; k0 < DHEAD; k0 += 16) {
        #pragma unroll
        for (int i = 0; i < 4; i++) {
            int idx = tid + i * 256;
            int m = idx >> 4, kk = idx & 15;
            Qsr[kk][m] = qr[(size_t)(bi_ + m) * DIMSZ + k0 + kk];
            Qsi[kk][m] = qi[(size_t)(bi_ + m) * DIMSZ + k0 + kk];
            Ksr[kk][m] = kr[(size_t)(bj + m) * DIMSZ + k0 + kk];
            Ksi[kk][m] = ki[(size_t)(bj + m) * DIMSZ + k0 + kk];
        }
        __syncthreads();
        #pragma unroll
        for (int kk = 0; kk < 16; kk++) {
            float4 q_r = *(const float4*)&Qsr[kk][ty * 4];
            float4 q_i = *(const float4*)&Qsi[kk][ty * 4];
            float4 k_r = *(const float4*)&Ksr[kk][tx * 4];
            float4 k_i = *(const float4*)&Ksi[kk][tx * 4];
            float qrv[4] = {q_r.x, q_r.y, q_r.z, q_r.w};
            float qiv[4] = {q_i.x, q_i.y, q_i.z, q_i.w};
            float krv[4] = {k_r.x, k_r.y, k_r.z, k_r.w};
            float kiv[4] = {k_i.x, k_i.y, k_i.z, k_i.w};
            #pragma unroll
            for (int i = 0; i < 4; i++)
                #pragma unroll
                for (int j = 0; j < 4; j++) {
                    acc[i][j] += qrv[i] * krv[j];
                    acc[i][j] += qiv[i] * kiv[j];
                }
        }
        __syncthreads();
    }
    #pragma unroll
    for (int i = 0; i < 4; i++)
        #pragma unroll
        for (int j = 0; j < 4; j++)
            s[(size_t)(bi_ + ty * 4 + i) * SEQ + bj + tx * 4 + j] = acc[i][j] * 0.125f;
}

// ---------------- softmax over last dim (1024) ----------------
__global__ __launch_bounds__(256) void softmax_kernel(float* __restrict__ S)
{
    float* row = S + (size_t)blockIdx.x * SEQ;
    const int t = threadIdx.x;
    __shared__ float red[256];
    float4 v = *(float4*)&row[t * 4];
    float m = fmaxf(fmaxf(v.x, v.y), fmaxf(v.z, v.w));
    red[t] = m; __syncthreads();
    for (int s = 128; s > 0; s >>= 1) {
        if (t < s) red[t] = fmaxf(red[t], red[t + s]);
        __syncthreads();
    }
    m = red[0]; __syncthreads();
    v.x = expf(v.x - m); v.y = expf(v.y - m);
    v.z = expf(v.z - m); v.w = expf(v.w - m);
    float sum = v.x + v.y + v.z + v.w;
    red[t] = sum; __syncthreads();
    for (int s = 128; s > 0; s >>= 1) {
        if (t < s) red[t] += red[t + s];
        __syncthreads();
    }
    float inv = 1.0f / red[0];
    v.x *= inv; v.y *= inv; v.z *= inv; v.w *= inv;
    *(float4*)&row[t * 4] = v;
}

// ---------------- out_f = attn @ Vf (attn real, Vf complex) ----------------
__global__ __launch_bounds__(256) void av_kernel(
    const float* __restrict__ S, const float* __restrict__ Vr, const float* __restrict__ Vi,
    float* __restrict__ Or, float* __restrict__ Oi)
{
    const int bh = blockIdx.z;
    const int b = bh >> 4, h = bh & 15;
    const float* a = S + (size_t)bh * SEQ * SEQ;
    const size_t vb = (size_t)b * SEQ * DIMSZ + h * DHEAD;
    const float* vr = Vr + vb; const float* vi = Vi + vb;
    float* outr = Or + vb; float* outi = Oi + vb;
    const int bi_ = blockIdx.x * 64;
    const int tid = threadIdx.x;
    const int tx = tid & 15, ty = tid >> 4;
    __shared__ float As[16][68], Vsr[16][68], Vsi[16][68];
    float accr[4][4] = {{0.f}}, acci[4][4] = {{0.f}};
    for (int k0 = 0; k0 < SEQ; k0 += 16) {
        #pragma unroll
        for (int i = 0; i < 4; i++) {
            int idx = tid + i * 256;
            int m = idx >> 4, kk = idx & 15;
            As[kk][m] = a[(size_t)(bi_ + m) * SEQ + k0 + kk];
            int n = idx & 63, k2 = idx >> 6;
            Vsr[k2][n] = vr[(size_t)(k0 + k2) * DIMSZ + n];
            Vsi[k2][n] = vi[(size_t)(k0 + k2) * DIMSZ + n];
        }
        __syncthreads();
        #pragma unroll
        for (int kk = 0; kk < 16; kk++) {
            float4 a4 = *(const float4*)&As[kk][ty * 4];
            float4 v_r = *(const float4*)&Vsr[kk][tx * 4];
            float4 v_i = *(const float4*)&Vsi[kk][tx * 4];
            float av[4] = {a4.x, a4.y, a4.z, a4.w};
            float vrv[4] = {v_r.x, v_r.y, v_r.z, v_r.w};
            float viv[4] = {v_i.x, v_i.y, v_i.z, v_i.w};
            #pragma unroll
            for (int i = 0; i < 4; i++)
                #pragma unroll
                for (int j = 0; j < 4; j++) {
                    accr[i][j] += av[i] * vrv[j];
                    acci[i][j] += av[i] * viv[j];
                }
        }
        __syncthreads();
    }
    #pragma unroll
    for (int i = 0; i < 4; i++)
        #pragma unroll
        for (int j = 0; j < 4; j++) {
            size_t o = (size_t)(bi_ + ty * 4 + i) * DIMSZ + tx * 4 + j;
            outr[o] = accr[i][j];
            outi[o] = acci[i][j];
        }
}

// ---------------- small elementwise kernels ----------------
__global__ __launch_bounds__(256) void scaleH_kernel(const float* __restrict__ H,
                                                     const float* __restrict__ dt,
                                                     float* __restrict__ M)
{
    int i = blockIdx.x * 256 + threadIdx.x;
    M[i] = H[i] * dt[0];
}

__global__ __launch_bounds__(256) void axpbI_kernel(const float* __restrict__ P,
                                                    float a, float b, float* __restrict__ T)
{
    int i = blockIdx.x * 256 + threadIdx.x;
    float v = a * P[i];
    int r = i >> 10, c = i & 1023;
    if (r == c) v += b;
    T[i] = v;
}

// ---------------- host launch ----------------
static float* symaddr(const void* sym)
{
    void* p = nullptr;
    cudaGetSymbolAddress(&p, sym);
    return (float*)p;
}

extern "C" void kernel_launch(void* const* d_in, const int* in_sizes, int n_in,
                              void* d_out, int out_size)
{
    const float* xr = (const float*)d_in[0];
    const float* xi = (const float*)d_in[1];
    const float* Wr_q = (const float*)d_in[2];  const float* Wi_q = (const float*)d_in[3];
    const float* br_q = (const float*)d_in[4];  const float* bi_q = (const float*)d_in[5];
    const float* Wr_k = (const float*)d_in[6];  const float* Wi_k = (const float*)d_in[7];
    const float* br_k = (const float*)d_in[8];  const float* bi_k = (const float*)d_in[9];
    const float* Wr_v = (const float*)d_in[10]; const float* Wi_v = (const float*)d_in[11];
    const float* br_v = (const float*)d_in[12]; const float* bi_v = (const float*)d_in[13];
    const float* Wr_o = (const float*)d_in[14]; const float* Wi_o = (const float*)d_in[15];
    const float* br_o = (const float*)d_in[16]; const float* bi_o = (const float*)d_in[17];
    const float* Wr_f1 = (const float*)d_in[18]; const float* Wi_f1 = (const float*)d_in[19];
    const float* br_f1 = (const float*)d_in[20]; const float* bi_f1 = (const float*)d_in[21];
    const float* Wr_f2 = (const float*)d_in[22]; const float* Wi_f2 = (const float*)d_in[23];
    const float* br_f2 = (const float*)d_in[24]; const float* bi_f2 = (const float*)d_in[25];
    const float* Hm = (const float*)d_in[26];
    const float* dt = (const float*)d_in[27];

    float* Qr = symaddr(g_Qr);   float* Qi = symaddr(g_Qi);
    float* Kr = symaddr(g_Kr);   float* Ki = symaddr(g_Ki);
    float* Vr = symaddr(g_Vr);   float* Vi = symaddr(g_Vi);
    float* Sb = symaddr(g_S);
    float* OFr = symaddr(g_OFr); float* OFi = symaddr(g_OFi);
    float* x1r = symaddr(g_x1r); float* x1i = symaddr(g_x1i);
    float* x2r = symaddr(g_x2r); float* x2i = symaddr(g_x2i);
    float* hr = symaddr(g_hr);   float* hi = symaddr(g_hi);
    float* Mx = symaddr(g_Mx);   float* P2 = symaddr(g_P2);
    float* T1 = symaddr(g_T1);   float* T2 = symaddr(g_T2);
    float* Uc = symaddr(g_Ucos); float* Us = symaddr(g_UsinN);

    dim3 blk(256);
    dim3 gP(DIMSZ / 64, MROWS / 64);      // (16, 32)
    dim3 gF(DIMSZ / 4, BATCH);            // (256, 2)
    dim3 gS(SEQ / 64, SEQ / 64, BATCH * HEADS);
    dim3 gA(SEQ / 64, 1, BATCH * HEADS);
    dim3 gR(DIMSZ / 64, DIMSZ / 64);      // (16, 16)
    dim3 gF1(HIDDEN / 64, MROWS / 64);    // (64, 32)

    // --- QKV projections ---
    cgemm_kernel<<<gP, blk>>>(xr, xi, Wr_q, Wi_q, br_q, bi_q, nullptr, nullptr,
                              Qr, Qi, MROWS, DIMSZ, DIMSZ, 0);
    cgemm_kernel<<<gP, blk>>>(xr, xi, Wr_k, Wi_k, br_k, bi_k, nullptr, nullptr,
                              Kr, Ki, MROWS, DIMSZ, DIMSZ, 0);
    cgemm_kernel<<<gP, blk>>>(xr, xi, Wr_v, Wi_v, br_v, bi_v, nullptr, nullptr,
                              Vr, Vi, MROWS, DIMSZ, DIMSZ, 0);

    // --- FFTs along sequence ---
    fft_kernel<<<gF, blk>>>(Qr, Qi, 0, 1.0f);
    fft_kernel<<<gF, blk>>>(Kr, Ki, 0, 1.0f);
    fft_kernel<<<gF, blk>>>(Vr, Vi, 0, 1.0f);

    // --- attention ---
    qk_kernel<<<gS, blk>>>(Qr, Qi, Kr, Ki, Sb);
    softmax_kernel<<<BATCH * HEADS * SEQ, blk>>>(Sb);
    av_kernel<<<gA, blk>>>(Sb, Vr, Vi, OFr, OFi);
    fft_kernel<<<gF, blk>>>(OFr, OFi, 1, 1.0f / (float)SEQ);

    // --- O projection + residual ---
    cgemm_kernel<<<gP, blk>>>(OFr, OFi, Wr_o, Wi_o, br_o, bi_o, xr, xi,
                              x1r, x1i, MROWS, DIMSZ, DIMSZ, 1);

    // --- FFN ---
    cgemm_kernel<<<gF1, blk>>>(x1r, x1i, Wr_f1, Wi_f1, br_f1, bi_f1, nullptr, nullptr,
                               hr, hi, MROWS, HIDDEN, DIMSZ, 2);
    cgemm_kernel<<<gP, blk>>>(hr, hi, Wr_f2, Wi_f2, br_f2, bi_f2, x1r, x1i,
                              x2r, x2i, MROWS, DIMSZ, HIDDEN, 1);

    // --- U = expm(-i H dt) = cos(dtH) - i sin(dtH), via Taylor/Horner in P2=(dtH)^2 ---
    scaleH_kernel<<<DIMSZ * DIMSZ / 256, blk>>>(Hm, dt, Mx);
    rgemm_kernel<<<gR, blk>>>(Mx, Mx, P2, 1.0f, 0.0f);
    // cos: ((c3*P2 + c2*I)*P2 + c1*I)*P2 + I, c3=-1/720, c2=1/24, c1=-1/2
    axpbI_kernel<<<DIMSZ * DIMSZ / 256, blk>>>(P2, -1.0f / 720.0f, 1.0f / 24.0f, T1);
    rgemm_kernel<<<gR, blk>>>(T1, P2, T2, 1.0f, -0.5f);
    rgemm_kernel<<<gR, blk>>>(T2, P2, Uc, 1.0f, 1.0f);
    // sin: M * (((s3*P2 + s2*I)*P2 + s1*I)*P2 + I), s3=-1/5040, s2=1/120, s1=-1/6
    axpbI_kernel<<<DIMSZ * DIMSZ / 256, blk>>>(P2, -1.0f / 5040.0f, 1.0f / 120.0f, T1);
    rgemm_kernel<<<gR, blk>>>(T1, P2, T2, 1.0f, -1.0f / 6.0f);
    rgemm_kernel<<<gR, blk>>>(T2, P2, T1, 1.0f, 1.0f);
    rgemm_kernel<<<gR, blk>>>(Mx, T1, Us, -1.0f, 0.0f);   // Us = -sin(dtH)

    // --- final: out = x2 @ U; U symmetric so U == U^T, reuse linear-layer GEMM ---
    float* outR = (float*)d_out;
    float* outI = outR + (size_t)MROWS * DIMSZ;
    cgemm_kernel<<<gP, blk>>>(x2r, x2i, Uc, Us, nullptr, nullptr, nullptr, nullptr,
                              outR, outI, MROWS, DIMSZ, DIMSZ, 0);
}

// round 11
// speedup vs baseline: 1.0525x; 1.0485x over previous
#include <cuda_runtime.h>
#include <cuda_bf16.h>
#include <math.h>
#include <stdint.h>

#define DIMSZ 1024
#define BATCH 2
#define SEQ 1024
#define HEADS 16
#define DHEAD 64
#define HIDDEN 4096
#define MROWS (BATCH*SEQ)          /* 2048 */
#define BND (MROWS*DIMSZ)          /* 2097152 */

// ---------------- scratch (__device__ globals; no allocation allowed) ----------------
__device__ float g_Qr[BND], g_Qi[BND];
__device__ float g_Kr[BND], g_Ki[BND];
__device__ float g_Vr[BND], g_Vi[BND];
__device__ float g_S[(size_t)BATCH*HEADS*SEQ*SEQ];   // 32 * 1024 * 1024
__device__ float g_OFr[BND], g_OFi[BND];
__device__ float g_x1r[BND], g_x1i[BND];
__device__ float g_x2r[BND], g_x2i[BND];
__device__ float g_hr[MROWS*HIDDEN], g_hi[MROWS*HIDDEN];
__device__ float g_Mx[DIMSZ*DIMSZ], g_P2[DIMSZ*DIMSZ];
__device__ float g_T1[DIMSZ*DIMSZ], g_T2[DIMSZ*DIMSZ];
__device__ float g_Ucos[DIMSZ*DIMSZ], g_UsinN[DIMSZ*DIMSZ];

__device__ __forceinline__ float gelu_f(float x) {
    return 0.5f * x * (1.0f + erff(x * 0.70710678118654752440f));
}

// split two consecutive floats into packed bf16x2 (hi) and packed bf16x2 (lo).
// low 16 bits hold the even-k element, high 16 bits the odd-k element.
__device__ __forceinline__ void split2(float f0, float f1, uint32_t& hi, uint32_t& lo) {
    __nv_bfloat16 h0 = __float2bfloat16_rn(f0);
    __nv_bfloat16 h1 = __float2bfloat16_rn(f1);
    float r0 = f0 - __bfloat162float(h0);
    float r1 = f1 - __bfloat162float(h1);
    __nv_bfloat16 l0 = __float2bfloat16_rn(r0);
    __nv_bfloat16 l1 = __float2bfloat16_rn(r1);
    hi = (uint32_t)__bfloat16_as_ushort(h0) | ((uint32_t)__bfloat16_as_ushort(h1) << 16);
    lo = (uint32_t)__bfloat16_as_ushort(l0) | ((uint32_t)__bfloat16_as_ushort(l1) << 16);
}

#define MMA_BF16(d, a, b) \
    asm volatile("mma.sync.aligned.m16n8k16.row.col.f32.bf16.bf16.f32 " \
        "{%0,%1,%2,%3}, {%4,%5,%6,%7}, {%8,%9}, {%0,%1,%2,%3};" \
        : "+f"(d[0]), "+f"(d[1]), "+f"(d[2]), "+f"(d[3]) \
        : "r"(a[0]), "r"(a[1]), "r"(a[2]), "r"(a[3]), "r"(b[0]), "r"(b[1]))

// A-fragment load from pair-array P[8][PAD]: rows (m0+g, m0+g+8), pairs (tg, tg+4)
#define LOAD_AFRAG(f, P, m0) \
    f[0] = P[tg][(m0) + g];     f[1] = P[tg][(m0) + g + 8]; \
    f[2] = P[tg + 4][(m0) + g]; f[3] = P[tg + 4][(m0) + g + 8]
// B-fragment: col n0+g, pairs (tg, tg+4)
#define LOAD_BFRAG(f, P, n0) \
    f[0] = P[tg][(n0) + g]; f[1] = P[tg + 4][(n0) + g]

// ====================================================================================
// bf16-split complex GEMM: C = A @ W^T (+bias)(+gelu)(+residual)   [fp32-accurate]
// A: [M,K] (Ar,Ai) row-major, W: [Nn,K] (Wr,Wi) row-major; C: [M,Nn]
// Block tile 128x64, 8 warps of 32x32. BK=16 (one m16n8k16 step per stage).
// flags bit0: residual, bit1: gelu
// ====================================================================================
__global__ __launch_bounds__(256, 1) void cgemm_tc(
    const float* __restrict__ Ar, const float* __restrict__ Ai,
    const float* __restrict__ Wr, const float* __restrict__ Wi,
    const float* __restrict__ br, const float* __restrict__ bi,
    const float* __restrict__ Rr, const float* __restrict__ Ri,
    float* __restrict__ Cr, float* __restrict__ Ci,
    int Nn, int K, int flags)
{
    __shared__ uint32_t Ah_r[8][136], Al_r[8][136], Ah_i[8][136], Al_i[8][136];
    __shared__ uint32_t Wh_r[8][72],  Wl_r[8][72],  Wh_i[8][72],  Wl_i[8][72];
    const int bm = blockIdx.y * 128, bn = blockIdx.x * 64;
    const int tid = threadIdx.x;
    const int warp = tid >> 5, lane = tid & 31;
    const int wm = (warp >> 1) * 32, wn = (warp & 1) * 32;
    const int g = lane >> 2, tg = lane & 3;
    const int arow = tid >> 2;          // 0..63
    const int kseg = (tid & 3) * 4;     // 0..12, 4 floats -> 2 pairs
    const int p0 = (tid & 3) * 2;

    float cr[2][4][4], ci[2][4][4];
    #pragma unroll
    for (int mt = 0; mt < 2; mt++)
        #pragma unroll
        for (int nt = 0; nt < 4; nt++)
            #pragma unroll
            for (int e = 0; e < 4; e++) { cr[mt][nt][e] = 0.f; ci[mt][nt][e] = 0.f; }

    for (int k0 = 0; k0 < K; k0 += 16) {
        // stage A (128 rows x 16 k)
        #pragma unroll
        for (int r = 0; r < 2; r++) {
            const int row = arow + r * 64;
            const float4 vr4 = *(const float4*)&Ar[(size_t)(bm + row) * K + k0 + kseg];
            const float4 vi4 = *(const float4*)&Ai[(size_t)(bm + row) * K + k0 + kseg];
            split2(vr4.x, vr4.y, Ah_r[p0][row],     Al_r[p0][row]);
            split2(vr4.z, vr4.w, Ah_r[p0 + 1][row], Al_r[p0 + 1][row]);
            split2(vi4.x, vi4.y, Ah_i[p0][row],     Al_i[p0][row]);
            split2(vi4.z, vi4.w, Ah_i[p0 + 1][row], Al_i[p0 + 1][row]);
        }
        // stage W (64 rows x 16 k)
        {
            const float4 vr4 = *(const float4*)&Wr[(size_t)(bn + arow) * K + k0 + kseg];
            const float4 vi4 = *(const float4*)&Wi[(size_t)(bn + arow) * K + k0 + kseg];
            split2(vr4.x, vr4.y, Wh_r[p0][arow],     Wl_r[p0][arow]);
            split2(vr4.z, vr4.w, Wh_r[p0 + 1][arow], Wl_r[p0 + 1][arow]);
            split2(vi4.x, vi4.y, Wh_i[p0][arow],     Wl_i[p0][arow]);
            split2(vi4.z, vi4.w, Wh_i[p0 + 1][arow], Wl_i[p0 + 1][arow]);
        }
        __syncthreads();

        uint32_t ahr[2][4], alr[2][4], ahi[2][4], ali[2][4];
        #pragma unroll
        for (int mt = 0; mt < 2; mt++) {
            const int m0 = wm + mt * 16;
            LOAD_AFRAG(ahr[mt], Ah_r, m0); LOAD_AFRAG(alr[mt], Al_r, m0);
            LOAD_AFRAG(ahi[mt], Ah_i, m0); LOAD_AFRAG(ali[mt], Al_i, m0);
        }
        #pragma unroll
        for (int nt = 0; nt < 4; nt++) {
            const int n0 = wn + nt * 8;
            uint32_t bhr[2], blr[2], bhi[2], bli[2], nhi[2], nli[2];
            LOAD_BFRAG(bhr, Wh_r, n0); LOAD_BFRAG(blr, Wl_r, n0);
            LOAD_BFRAG(bhi, Wh_i, n0); LOAD_BFRAG(bli, Wl_i, n0);
            nhi[0] = bhi[0] ^ 0x80008000u; nhi[1] = bhi[1] ^ 0x80008000u;
            nli[0] = bli[0] ^ 0x80008000u; nli[1] = bli[1] ^ 0x80008000u;
            #pragma unroll
            for (int mt = 0; mt < 2; mt++) {
                // cr += ar*wr - ai*wi
                MMA_BF16(cr[mt][nt], ahr[mt], bhr);
                MMA_BF16(cr[mt][nt], ahr[mt], blr);
                MMA_BF16(cr[mt][nt], alr[mt], bhr);
                MMA_BF16(cr[mt][nt], ahi[mt], nhi);
                MMA_BF16(cr[mt][nt], ahi[mt], nli);
                MMA_BF16(cr[mt][nt], ali[mt], nhi);
                // ci += ar*wi + ai*wr
                MMA_BF16(ci[mt][nt], ahr[mt], bhi);
                MMA_BF16(ci[mt][nt], ahr[mt], bli);
                MMA_BF16(ci[mt][nt], alr[mt], bhi);
                MMA_BF16(ci[mt][nt], ahi[mt], bhr);
                MMA_BF16(ci[mt][nt], ahi[mt], blr);
                MMA_BF16(ci[mt][nt], ali[mt], bhr);
            }
        }
        __syncthreads();
    }
    // epilogue
    #pragma unroll
    for (int mt = 0; mt < 2; mt++)
        #pragma unroll
        for (int nt = 0; nt < 4; nt++)
            #pragma unroll
            for (int e = 0; e < 4; e++) {
                const int m = bm + wm + mt * 16 + g + ((e >> 1) ? 8 : 0);
                const int n = bn + wn + nt * 8 + tg * 2 + (e & 1);
                float vr = cr[mt][nt][e], vi = ci[mt][nt][e];
                if (br) { vr += br[n]; vi += bi[n]; }
                if (flags & 2) { vr = gelu_f(vr); vi = gelu_f(vi); }
                const size_t o = (size_t)m * Nn + n;
                if (flags & 1) { vr += Rr[o]; vi += Ri[o]; }
                Cr[o] = vr; Ci[o] = vi;
            }
}

// ====================================================================================
// bf16-split scores: S[b,h,i,j] = 0.125 * (Qr.Kr + Qi.Ki) over dh=64
// ====================================================================================
__global__ __launch_bounds__(256, 1) void qk_tc(
    const float* __restrict__ Qr, const float* __restrict__ Qi,
    const float* __restrict__ Kr, const float* __restrict__ Ki,
    float* __restrict__ S)
{
    __shared__ uint32_t Ah_r[8][136], Al_r[8][136], Ah_i[8][136], Al_i[8][136];
    __shared__ uint32_t Wh_r[8][72],  Wl_r[8][72],  Wh_i[8][72],  Wl_i[8][72];
    const int bh = blockIdx.z;
    const int b = bh >> 4, h = bh & 15;
    const size_t xb = (size_t)b * SEQ * DIMSZ + h * DHEAD;
    const float* qr = Qr + xb; const float* qi = Qi + xb;
    const float* kr = Kr + xb; const float* ki = Ki + xb;
    float* s = S + (size_t)bh * SEQ * SEQ;
    const int bm = blockIdx.y * 128, bn = blockIdx.x * 64;
    const int tid = threadIdx.x;
    const int warp = tid >> 5, lane = tid & 31;
    const int wm = (warp >> 1) * 32, wn = (warp & 1) * 32;
    const int g = lane >> 2, tg = lane & 3;
    const int arow = tid >> 2;
    const int kseg = (tid & 3) * 4;
    const int p0 = (tid & 3) * 2;

    float acc[2][4][4];
    #pragma unroll
    for (int mt = 0; mt < 2; mt++)
        #pragma unroll
        for (int nt = 0; nt < 4; nt++)
            #pragma unroll
            for (int e = 0; e < 4; e++) acc[mt][nt][e] = 0.f;

    #pragma unroll
    for (int k0 = 0; k0 < DHEAD; k0 += 16) {
        #pragma unroll
        for (int r = 0; r < 2; r++) {
            const int row = arow + r * 64;
            const float4 vr4 = *(const float4*)&qr[(size_t)(bm + row) * DIMSZ + k0 + kseg];
            const float4 vi4 = *(const float4*)&qi[(size_t)(bm + row) * DIMSZ + k0 + kseg];
            split2(vr4.x, vr4.y, Ah_r[p0][row],     Al_r[p0][row]);
            split2(vr4.z, vr4.w, Ah_r[p0 + 1][row], Al_r[p0 + 1][row]);
            split2(vi4.x, vi4.y, Ah_i[p0][row],     Al_i[p0][row]);
            split2(vi4.z, vi4.w, Ah_i[p0 + 1][row], Al_i[p0 + 1][row]);
        }
        {
            const float4 vr4 = *(const float4*)&kr[(size_t)(bn + arow) * DIMSZ + k0 + kseg];
            const float4 vi4 = *(const float4*)&ki[(size_t)(bn + arow) * DIMSZ + k0 + kseg];
            split2(vr4.x, vr4.y, Wh_r[p0][arow],     Wl_r[p0][arow]);
            split2(vr4.z, vr4.w, Wh_r[p0 + 1][arow], Wl_r[p0 + 1][arow]);
            split2(vi4.x, vi4.y, Wh_i[p0][arow],     Wl_i[p0][arow]);
            split2(vi4.z, vi4.w, Wh_i[p0 + 1][arow], Wl_i[p0 + 1][arow]);
        }
        __syncthreads();

        uint32_t ahr[2][4], alr[2][4], ahi[2][4], ali[2][4];
        #pragma unroll
        for (int mt = 0; mt < 2; mt++) {
            const int m0 = wm + mt * 16;
            LOAD_AFRAG(ahr[mt], Ah_r, m0); LOAD_AFRAG(alr[mt], Al_r, m0);
            LOAD_AFRAG(ahi[mt], Ah_i, m0); LOAD_AFRAG(ali[mt], Al_i, m0);
        }
        #pragma unroll
        for (int nt = 0; nt < 4; nt++) {
            const int n0 = wn + nt * 8;
            uint32_t bhr[2], blr[2], bhi[2], bli[2];
            LOAD_BFRAG(bhr, Wh_r, n0); LOAD_BFRAG(blr, Wl_r, n0);
            LOAD_BFRAG(bhi, Wh_i, n0); LOAD_BFRAG(bli, Wl_i, n0);
            #pragma unroll
            for (int mt = 0; mt < 2; mt++) {
                MMA_BF16(acc[mt][nt], ahr[mt], bhr);
                MMA_BF16(acc[mt][nt], ahr[mt], blr);
                MMA_BF16(acc[mt][nt], alr[mt], bhr);
                MMA_BF16(acc[mt][nt], ahi[mt], bhi);
                MMA_BF16(acc[mt][nt], ahi[mt], bli);
                MMA_BF16(acc[mt][nt], ali[mt], bhi);
            }
        }
        __syncthreads();
    }
    #pragma unroll
    for (int mt = 0; mt < 2; mt++)
        #pragma unroll
        for (int nt = 0; nt < 4; nt++)
            #pragma unroll
            for (int e = 0; e < 4; e++) {
                const int m = bm + wm + mt * 16 + g + ((e >> 1) ? 8 : 0);
                const int n = bn + wn + nt * 8 + tg * 2 + (e & 1);
                s[(size_t)m * SEQ + n] = acc[mt][nt][e] * 0.125f;
            }
}

// ====================================================================================
// bf16-split out_f = attn @ Vf (attn real [1024x1024], Vf complex [1024x64])
// ====================================================================================
__global__ __launch_bounds__(256, 1) void av_tc(
    const float* __restrict__ S, const float* __restrict__ Vr, const float* __restrict__ Vi,
    float* __restrict__ Or, float* __restrict__ Oi)
{
    __shared__ uint32_t Ah[8][136], Al[8][136];
    __shared__ uint32_t Vh_r[8][72], Vl_r[8][72], Vh_i[8][72], Vl_i[8][72];
    const int bh = blockIdx.z;
    const int b = bh >> 4, h = bh & 15;
    const float* a = S + (size_t)bh * SEQ * SEQ;
    const size_t vb = (size_t)b * SEQ * DIMSZ + h * DHEAD;
    const float* vr = Vr + vb; const float* vi = Vi + vb;
    float* outr = Or + vb; float* outi = Oi + vb;
    const int bm = blockIdx.x * 128;
    const int tid = threadIdx.x;
    const int warp = tid >> 5, lane = tid & 31;
    const int wm = (warp >> 1) * 32, wn = (warp & 1) * 32;
    const int g = lane >> 2, tg = lane & 3;
    const int arow = tid >> 2;
    const int kseg = (tid & 3) * 4;
    const int p0 = (tid & 3) * 2;
    const int vp = tid >> 5;              // 0..7   (k-pair for V staging)
    const int vn = (tid & 31) * 2;        // 0..62  (2 cols per thread)

    float or_[2][4][4], oi_[2][4][4];
    #pragma unroll
    for (int mt = 0; mt < 2; mt++)
        #pragma unroll
        for (int nt = 0; nt < 4; nt++)
            #pragma unroll
            for (int e = 0; e < 4; e++) { or_[mt][nt][e] = 0.f; oi_[mt][nt][e] = 0.f; }

    for (int k0 = 0; k0 < SEQ; k0 += 16) {
        #pragma unroll
        for (int r = 0; r < 2; r++) {
            const int row = arow + r * 64;
            const float4 v4 = *(const float4*)&a[(size_t)(bm + row) * SEQ + k0 + kseg];
            split2(v4.x, v4.y, Ah[p0][row],     Al[p0][row]);
            split2(v4.z, v4.w, Ah[p0 + 1][row], Al[p0 + 1][row]);
        }
        {
            // V pair vp: global rows k0+2vp, k0+2vp+1; cols vn, vn+1
            const float2 r0 = *(const float2*)&vr[(size_t)(k0 + 2 * vp) * DIMSZ + vn];
            const float2 r1 = *(const float2*)&vr[(size_t)(k0 + 2 * vp + 1) * DIMSZ + vn];
            const float2 i0 = *(const float2*)&vi[(size_t)(k0 + 2 * vp) * DIMSZ + vn];
            const float2 i1 = *(const float2*)&vi[(size_t)(k0 + 2 * vp + 1) * DIMSZ + vn];
            split2(r0.x, r1.x, Vh_r[vp][vn],     Vl_r[vp][vn]);
            split2(r0.y, r1.y, Vh_r[vp][vn + 1], Vl_r[vp][vn + 1]);
            split2(i0.x, i1.x, Vh_i[vp][vn],     Vl_i[vp][vn]);
            split2(i0.y, i1.y, Vh_i[vp][vn + 1], Vl_i[vp][vn + 1]);
        }
        __syncthreads();

        uint32_t ah[2][4], al[2][4];
        #pragma unroll
        for (int mt = 0; mt < 2; mt++) {
            const int m0 = wm + mt * 16;
            LOAD_AFRAG(ah[mt], Ah, m0); LOAD_AFRAG(al[mt], Al, m0);
        }
        #pragma unroll
        for (int nt = 0; nt < 4; nt++) {
            const int n0 = wn + nt * 8;
            uint32_t bhr[2], blr[2], bhi[2], bli[2];
            LOAD_BFRAG(bhr, Vh_r, n0); LOAD_BFRAG(blr, Vl_r, n0);
            LOAD_BFRAG(bhi, Vh_i, n0); LOAD_BFRAG(bli, Vl_i, n0);
            #pragma unroll
            for (int mt = 0; mt < 2; mt++) {
                MMA_BF16(or_[mt][nt], ah[mt], bhr);
                MMA_BF16(or_[mt][nt], ah[mt], blr);
                MMA_BF16(or_[mt][nt], al[mt], bhr);
                MMA_BF16(oi_[mt][nt], ah[mt], bhi);
                MMA_BF16(oi_[mt][nt], ah[mt], bli);
                MMA_BF16(oi_[mt][nt], al[mt], bhi);
            }
        }
        __syncthreads();
    }
    #pragma unroll
    for (int mt = 0; mt < 2; mt++)
        #pragma unroll
        for (int nt = 0; nt < 4; nt++)
            #pragma unroll
            for (int e = 0; e < 4; e++) {
                const int m = bm + wm + mt * 16 + g + ((e >> 1) ? 8 : 0);
                const int n = wn + nt * 8 + tg * 2 + (e & 1);
                const size_t o = (size_t)m * DIMSZ + n;
                outr[o] = or_[mt][nt][e];
                outi[o] = oi_[mt][nt][e];
            }
}

// ---------------- real GEMM (1024^3): C = scl*(A @ B) + alpha*I ----------------
__global__ __launch_bounds__(256) void rgemm_kernel(
    const float* __restrict__ A, const float* __restrict__ Bm,
    float* __restrict__ C, float scl, float alpha)
{
    __shared__ float As[16][68], Bs[16][68];
    const int bm = blockIdx.y * 64, bn = blockIdx.x * 64;
    const int tid = threadIdx.x;
    const int tx = tid & 15, ty = tid >> 4;
    float acc[4][4] = {{0.f}};
    for (int k0 = 0; k0 < DIMSZ; k0 += 16) {
        #pragma unroll
        for (int i = 0; i < 4; i++) {
            int idx = tid + i * 256;
            int m = idx >> 4, kk = idx & 15;
            As[kk][m] = A[(size_t)(bm + m) * DIMSZ + k0 + kk];
            int n = idx & 63, k2 = idx >> 6;
            Bs[k2][n] = Bm[(size_t)(k0 + k2) * DIMSZ + bn + n];
        }
        __syncthreads();
        #pragma unroll
        for (int kk = 0; kk < 16; kk++) {
            float4 a4 = *(const float4*)&As[kk][ty * 4];
            float4 b4 = *(const float4*)&Bs[kk][tx * 4];
            float a[4] = {a4.x, a4.y, a4.z, a4.w};
            float b[4] = {b4.x, b4.y, b4.z, b4.w};
            #pragma unroll
            for (int i = 0; i < 4; i++)
                #pragma unroll
                for (int j = 0; j < 4; j++)
                    acc[i][j] += a[i] * b[j];
        }
        __syncthreads();
    }
    #pragma unroll
    for (int i = 0; i < 4; i++)
        #pragma unroll
        for (int j = 0; j < 4; j++) {
            int m = bm + ty * 4 + i, n = bn + tx * 4 + j;
            C[(size_t)m * DIMSZ + n] = scl * acc[i][j] + ((m == n) ? alpha : 0.f);
        }
}

// ---------------- FFT along seq axis ----------------
__global__ __launch_bounds__(256) void fft_kernel(float* __restrict__ re, float* __restrict__ im,
                                                  int inv, float scale)
{
    __shared__ float sr[SEQ * 4], si[SEQ * 4];
    const int c0 = blockIdx.x * 4;
    const int b = blockIdx.y;
    const size_t base = (size_t)b * SEQ * DIMSZ;
    const int tid = threadIdx.x;
    const float sgn = inv ? 1.0f : -1.0f;

    for (int i = tid; i < SEQ * 4; i += 256) {
        int n = i >> 2, c = i & 3;
        int rn = __brev((unsigned)n) >> 22;
        size_t g = base + (size_t)n * DIMSZ + c0 + c;
        sr[rn * 4 + c] = re[g];
        si[rn * 4 + c] = im[g];
    }
    __syncthreads();

    for (int s = 1; s <= 10; s++) {
        int half = 1 << (s - 1);
        float angstep = sgn * 6.283185307179586f / (float)(1 << s);
        for (int i = tid; i < 2048; i += 256) {
            int j = i >> 2, c = i & 3;
            int k = j & (half - 1);
            int grp = j >> (s - 1);
            int i0 = ((grp << s) + k) * 4 + c;
            int i1 = i0 + half * 4;
            float cw, sw;
            sincosf(angstep * (float)k, &sw, &cw);
            float ur = sr[i0], ui = si[i0];
            float vr = sr[i1], vi = si[i1];
            float tr = vr * cw - vi * sw;
            float ti = vr * sw + vi * cw;
            sr[i0] = ur + tr; si[i0] = ui + ti;
            sr[i1] = ur - tr; si[i1] = ui - ti;
        }
        __syncthreads();
    }

    for (int i = tid; i < SEQ * 4; i += 256) {
        int n = i >> 2, c = i & 3;
        size_t g = base + (size_t)n * DIMSZ + c0 + c;
        re[g] = sr[n * 4 + c] * scale;
        im[g] = si[n * 4 + c] * scale;
    }
}

// ---------------- softmax over last dim (1024) ----------------
__global__ __launch_bounds__(256) void softmax_kernel(float* __restrict__ S)
{
    float* row = S + (size_t)blockIdx.x * SEQ;
    const int t = threadIdx.x;
    __shared__ float red[256];
    float4 v = *(float4*)&row[t * 4];
    float m = fmaxf(fmaxf(v.x, v.y), fmaxf(v.z, v.w));
    red[t] = m; __syncthreads();
    for (int s = 128; s > 0; s >>= 1) {
        if (t < s) red[t] = fmaxf(red[t], red[t + s]);
        __syncthreads();
    }
    m = red[0]; __syncthreads();
    v.x = expf(v.x - m); v.y = expf(v.y - m);
    v.z = expf(v.z - m); v.w = expf(v.w - m);
    float sum = v.x + v.y + v.z + v.w;
    red[t] = sum; __syncthreads();
    for (int s = 128; s > 0; s >>= 1) {
        if (t < s) red[t] += red[t + s];
        __syncthreads();
    }
    float inv = 1.0f / red[0];
    v.x *= inv; v.y *= inv; v.z *= inv; v.w *= inv;
    *(float4*)&row[t * 4] = v;
}

// ---------------- small elementwise kernels ----------------
__global__ __launch_bounds__(256) void scaleH_kernel(const float* __restrict__ H,
                                                     const float* __restrict__ dt,
                                                     float* __restrict__ M)
{
    int i = blockIdx.x * 256 + threadIdx.x;
    M[i] = H[i] * dt[0];
}

__global__ __launch_bounds__(256) void axpbI_kernel(const float* __restrict__ P,
                                                    float a, float b, float* __restrict__ T)
{
    int i = blockIdx.x * 256 + threadIdx.x;
    float v = a * P[i];
    int r = i >> 10, c = i & 1023;
    if (r == c) v += b;
    T[i] = v;
}

// ---------------- host launch ----------------
static float* symaddr(const void* sym)
{
    void* p = nullptr;
    cudaGetSymbolAddress(&p, sym);
    return (float*)p;
}

extern "C" void kernel_launch(void* const* d_in, const int* in_sizes, int n_in,
                              void* d_out, int out_size)
{
    const float* xr = (const float*)d_in[0];
    const float* xi = (const float*)d_in[1];
    const float* Wr_q = (const float*)d_in[2];  const float* Wi_q = (const float*)d_in[3];
    const float* br_q = (const float*)d_in[4];  const float* bi_q = (const float*)d_in[5];
    const float* Wr_k = (const float*)d_in[6];  const float* Wi_k = (const float*)d_in[7];
    const float* br_k = (const float*)d_in[8];  const float* bi_k = (const float*)d_in[9];
    const float* Wr_v = (const float*)d_in[10]; const float* Wi_v = (const float*)d_in[11];
    const float* br_v = (const float*)d_in[12]; const float* bi_v = (const float*)d_in[13];
    const float* Wr_o = (const float*)d_in[14]; const float* Wi_o = (const float*)d_in[15];
    const float* br_o = (const float*)d_in[16]; const float* bi_o = (const float*)d_in[17];
    const float* Wr_f1 = (const float*)d_in[18]; const float* Wi_f1 = (const float*)d_in[19];
    const float* br_f1 = (const float*)d_in[20]; const float* bi_f1 = (const float*)d_in[21];
    const float* Wr_f2 = (const float*)d_in[22]; const float* Wi_f2 = (const float*)d_in[23];
    const float* br_f2 = (const float*)d_in[24]; const float* bi_f2 = (const float*)d_in[25];
    const float* Hm = (const float*)d_in[26];
    const float* dt = (const float*)d_in[27];

    float* Qr = symaddr(g_Qr);   float* Qi = symaddr(g_Qi);
    float* Kr = symaddr(g_Kr);   float* Ki = symaddr(g_Ki);
    float* Vr = symaddr(g_Vr);   float* Vi = symaddr(g_Vi);
    float* Sb = symaddr(g_S);
    float* OFr = symaddr(g_OFr); float* OFi = symaddr(g_OFi);
    float* x1r = symaddr(g_x1r); float* x1i = symaddr(g_x1i);
    float* x2r = symaddr(g_x2r); float* x2i = symaddr(g_x2i);
    float* hr = symaddr(g_hr);   float* hi = symaddr(g_hi);
    float* Mx = symaddr(g_Mx);   float* P2 = symaddr(g_P2);
    float* T1 = symaddr(g_T1);   float* T2 = symaddr(g_T2);
    float* Uc = symaddr(g_Ucos); float* Us = symaddr(g_UsinN);

    dim3 blk(256);
    dim3 gP(DIMSZ / 64, MROWS / 128);      // (16, 16)
    dim3 gF(DIMSZ / 4, BATCH);             // (256, 2)
    dim3 gS(SEQ / 64, SEQ / 128, BATCH * HEADS);   // (16, 8, 32)
    dim3 gA(SEQ / 128, 1, BATCH * HEADS);          // (8, 1, 32)
    dim3 gR(DIMSZ / 64, DIMSZ / 64);       // (16, 16)
    dim3 gF1(HIDDEN / 64, MROWS / 128);    // (64, 16)

    // --- QKV projections (tensor core, bf16-split fp32 emulation) ---
    cgemm_tc<<<gP, blk>>>(xr, xi, Wr_q, Wi_q, br_q, bi_q, nullptr, nullptr,
                          Qr, Qi, DIMSZ, DIMSZ, 0);
    cgemm_tc<<<gP, blk>>>(xr, xi, Wr_k, Wi_k, br_k, bi_k, nullptr, nullptr,
                          Kr, Ki, DIMSZ, DIMSZ, 0);
    cgemm_tc<<<gP, blk>>>(xr, xi, Wr_v, Wi_v, br_v, bi_v, nullptr, nullptr,
                          Vr, Vi, DIMSZ, DIMSZ, 0);

    // --- FFTs along sequence ---
    fft_kernel<<<gF, blk>>>(Qr, Qi, 0, 1.0f);
    fft_kernel<<<gF, blk>>>(Kr, Ki, 0, 1.0f);
    fft_kernel<<<gF, blk>>>(Vr, Vi, 0, 1.0f);

    // --- attention ---
    qk_tc<<<gS, blk>>>(Qr, Qi, Kr, Ki, Sb);
    softmax_kernel<<<BATCH * HEADS * SEQ, blk>>>(Sb);
    av_tc<<<gA, blk>>>(Sb, Vr, Vi, OFr, OFi);
    fft_kernel<<<gF, blk>>>(OFr, OFi, 1, 1.0f / (float)SEQ);

    // --- O projection + residual ---
    cgemm_tc<<<gP, blk>>>(OFr, OFi, Wr_o, Wi_o, br_o, bi_o, xr, xi,
                          x1r, x1i, DIMSZ, DIMSZ, 1);

    // --- FFN ---
    cgemm_tc<<<gF1, blk>>>(x1r, x1i, Wr_f1, Wi_f1, br_f1, bi_f1, nullptr, nullptr,
                           hr, hi, HIDDEN, DIMSZ, 2);
    cgemm_tc<<<gP, blk>>>(hr, hi, Wr_f2, Wi_f2, br_f2, bi_f2, x1r, x1i,
                          x2r, x2i, DIMSZ, HIDDEN, 1);

    // --- U = expm(-i H dt) = cos(dtH) - i sin(dtH), via Taylor/Horner in P2=(dtH)^2 ---
    scaleH_kernel<<<DIMSZ * DIMSZ / 256, blk>>>(Hm, dt, Mx);
    rgemm_kernel<<<gR, blk>>>(Mx, Mx, P2, 1.0f, 0.0f);
    axpbI_kernel<<<DIMSZ * DIMSZ / 256, blk>>>(P2, -1.0f / 720.0f, 1.0f / 24.0f, T1);
    rgemm_kernel<<<gR, blk>>>(T1, P2, T2, 1.0f, -0.5f);
    rgemm_kernel<<<gR, blk>>>(T2, P2, Uc, 1.0f, 1.0f);
    axpbI_kernel<<<DIMSZ * DIMSZ / 256, blk>>>(P2, -1.0f / 5040.0f, 1.0f / 120.0f, T1);
    rgemm_kernel<<<gR, blk>>>(T1, P2, T2, 1.0f, -1.0f / 6.0f);
    rgemm_kernel<<<gR, blk>>>(T2, P2, T1, 1.0f, 1.0f);
    rgemm_kernel<<<gR, blk>>>(Mx, T1, Us, -1.0f, 0.0f);   // Us = -sin(dtH)

    // --- final: out = x2 @ U; U symmetric so U == U^T, reuse complex GEMM ---
    float* outR = (float*)d_out;
    float* outI = outR + (size_t)MROWS * DIMSZ;
    cgemm_tc<<<gP, blk>>>(x2r, x2i, Uc, Us, nullptr, nullptr, nullptr, nullptr,
                          outR, outI, DIMSZ, DIMSZ, 0);
}

// round 15
// speedup vs baseline: 1.6599x; 1.5771x over previous
#include <cuda_runtime.h>
#include <cuda_bf16.h>
#include <math.h>
#include <stdint.h>

#define DIMSZ 1024
#define BATCH 2
#define SEQ 1024
#define HEADS 16
#define DHEAD 64
#define HIDDEN 4096
#define MROWS (BATCH*SEQ)          /* 2048 */
#define BND (MROWS*DIMSZ)          /* 2097152 */

// ---------------- scratch (__device__ globals; no allocation allowed) ----------------
__device__ float g_Qr[BND], g_Qi[BND];
__device__ float g_Kr[BND], g_Ki[BND];
__device__ float g_Vr[BND], g_Vi[BND];
__device__ float g_S[(size_t)BATCH*HEADS*SEQ*SEQ];   // 32 * 1024 * 1024
__device__ float g_OFr[BND], g_OFi[BND];
__device__ float g_x1r[BND], g_x1i[BND];
__device__ float g_x2r[BND], g_x2i[BND];
__device__ float g_hr[MROWS*HIDDEN], g_hi[MROWS*HIDDEN];
__device__ float g_Mx[DIMSZ*DIMSZ], g_P2[DIMSZ*DIMSZ];
__device__ float g_T1[DIMSZ*DIMSZ], g_T2[DIMSZ*DIMSZ];
__device__ float g_Ucos[DIMSZ*DIMSZ], g_UsinN[DIMSZ*DIMSZ];

__device__ __forceinline__ float gelu_f(float x) {
    return 0.5f * x * (1.0f + erff(x * 0.70710678118654752440f));
}

// split two consecutive floats into packed bf16x2 (hi) and packed bf16x2 (lo).
__device__ __forceinline__ void split2(float f0, float f1, uint32_t& hi, uint32_t& lo) {
    __nv_bfloat16 h0 = __float2bfloat16_rn(f0);
    __nv_bfloat16 h1 = __float2bfloat16_rn(f1);
    float r0 = f0 - __bfloat162float(h0);
    float r1 = f1 - __bfloat162float(h1);
    __nv_bfloat16 l0 = __float2bfloat16_rn(r0);
    __nv_bfloat16 l1 = __float2bfloat16_rn(r1);
    hi = (uint32_t)__bfloat16_as_ushort(h0) | ((uint32_t)__bfloat16_as_ushort(h1) << 16);
    lo = (uint32_t)__bfloat16_as_ushort(l0) | ((uint32_t)__bfloat16_as_ushort(l1) << 16);
}

#define MMA_BF16(d, a, b) \
    asm volatile("mma.sync.aligned.m16n8k16.row.col.f32.bf16.bf16.f32 " \
        "{%0,%1,%2,%3}, {%4,%5,%6,%7}, {%8,%9}, {%0,%1,%2,%3};" \
        : "+f"(d[0]), "+f"(d[1]), "+f"(d[2]), "+f"(d[3]) \
        : "r"(a[0]), "r"(a[1]), "r"(a[2]), "r"(a[3]), "r"(b[0]), "r"(b[1]))

#define LOAD_AFRAG(f, P, m0) \
    f[0] = P[tg][(m0) + g];     f[1] = P[tg][(m0) + g + 8]; \
    f[2] = P[tg + 4][(m0) + g]; f[3] = P[tg + 4][(m0) + g + 8]
#define LOAD_BFRAG(f, P, n0) \
    f[0] = P[tg][(n0) + g]; f[1] = P[tg + 4][(n0) + g]

// ====================================================================================
// bf16-split Karatsuba complex GEMM: C = A @ W^T (+bias)(+gelu)(+residual)
// t1 = ar*wr, t2 = ai*wi, t3 = (ar+ai)*(wr+wi); cr = t1-t2, ci = t3-t1-t2
// Block tile 128x64, 8 warps of 32x32, BK=16; register-prefetch double buffering.
// flags bit0: residual, bit1: gelu
// ====================================================================================
__global__ __launch_bounds__(256, 1) void cgemm_tc(
    const float* __restrict__ Ar, const float* __restrict__ Ai,
    const float* __restrict__ Wr, const float* __restrict__ Wi,
    const float* __restrict__ br, const float* __restrict__ bi,
    const float* __restrict__ Rr, const float* __restrict__ Ri,
    float* __restrict__ Cr, float* __restrict__ Ci,
    int Nn, int K, int flags)
{
    __shared__ uint32_t Ah_r[8][136], Al_r[8][136];
    __shared__ uint32_t Ah_i[8][136], Al_i[8][136];
    __shared__ uint32_t Ah_s[8][136], Al_s[8][136];
    __shared__ uint32_t Wh_r[8][72],  Wl_r[8][72];
    __shared__ uint32_t Wh_i[8][72],  Wl_i[8][72];
    __shared__ uint32_t Wh_s[8][72],  Wl_s[8][72];
    const int bm = blockIdx.y * 128, bn = blockIdx.x * 64;
    const int tid = threadIdx.x;
    const int warp = tid >> 5, lane = tid & 31;
    const int wm = (warp >> 1) * 32, wn = (warp & 1) * 32;
    const int g = lane >> 2, tg = lane & 3;
    const int arow = tid >> 2;          // 0..63
    const int kseg = (tid & 3) * 4;
    const int p0 = (tid & 3) * 2;

    const float* pa_r0 = &Ar[(size_t)(bm + arow) * K + kseg];
    const float* pa_r1 = &Ar[(size_t)(bm + arow + 64) * K + kseg];
    const float* pa_i0 = &Ai[(size_t)(bm + arow) * K + kseg];
    const float* pa_i1 = &Ai[(size_t)(bm + arow + 64) * K + kseg];
    const float* pw_r  = &Wr[(size_t)(bn + arow) * K + kseg];
    const float* pw_i  = &Wi[(size_t)(bn + arow) * K + kseg];

    float t1[2][4][4], t2[2][4][4], t3[2][4][4];
    #pragma unroll
    for (int mt = 0; mt < 2; mt++)
        #pragma unroll
        for (int nt = 0; nt < 4; nt++)
            #pragma unroll
            for (int e = 0; e < 4; e++) { t1[mt][nt][e] = 0.f; t2[mt][nt][e] = 0.f; t3[mt][nt][e] = 0.f; }

    // prefetch stage 0
    float4 fAr[2], fAi[2], fWr, fWi;
    fAr[0] = *(const float4*)pa_r0; fAr[1] = *(const float4*)pa_r1;
    fAi[0] = *(const float4*)pa_i0; fAi[1] = *(const float4*)pa_i1;
    fWr = *(const float4*)pw_r;     fWi = *(const float4*)pw_i;

    for (int k0 = 0; k0 < K; k0 += 16) {
        // stage from prefetch registers
        #pragma unroll
        for (int r = 0; r < 2; r++) {
            const int row = arow + r * 64;
            split2(fAr[r].x, fAr[r].y, Ah_r[p0][row],     Al_r[p0][row]);
            split2(fAr[r].z, fAr[r].w, Ah_r[p0 + 1][row], Al_r[p0 + 1][row]);
            split2(fAi[r].x, fAi[r].y, Ah_i[p0][row],     Al_i[p0][row]);
            split2(fAi[r].z, fAi[r].w, Ah_i[p0 + 1][row], Al_i[p0 + 1][row]);
            split2(fAr[r].x + fAi[r].x, fAr[r].y + fAi[r].y, Ah_s[p0][row],     Al_s[p0][row]);
            split2(fAr[r].z + fAi[r].z, fAr[r].w + fAi[r].w, Ah_s[p0 + 1][row], Al_s[p0 + 1][row]);
        }
        split2(fWr.x, fWr.y, Wh_r[p0][arow],     Wl_r[p0][arow]);
        split2(fWr.z, fWr.w, Wh_r[p0 + 1][arow], Wl_r[p0 + 1][arow]);
        split2(fWi.x, fWi.y, Wh_i[p0][arow],     Wl_i[p0][arow]);
        split2(fWi.z, fWi.w, Wh_i[p0 + 1][arow], Wl_i[p0 + 1][arow]);
        split2(fWr.x + fWi.x, fWr.y + fWi.y, Wh_s[p0][arow],     Wl_s[p0][arow]);
        split2(fWr.z + fWi.z, fWr.w + fWi.w, Wh_s[p0 + 1][arow], Wl_s[p0 + 1][arow]);
        __syncthreads();

        // prefetch next stage (overlaps with MMA phase below)
        if (k0 + 16 < K) {
            const int kn = k0 + 16;
            fAr[0] = *(const float4*)(pa_r0 + kn); fAr[1] = *(const float4*)(pa_r1 + kn);
            fAi[0] = *(const float4*)(pa_i0 + kn); fAi[1] = *(const float4*)(pa_i1 + kn);
            fWr = *(const float4*)(pw_r + kn);     fWi = *(const float4*)(pw_i + kn);
        }

        uint32_t ahr[2][4], alr[2][4], ahi[2][4], ali[2][4], ahs[2][4], als[2][4];
        #pragma unroll
        for (int mt = 0; mt < 2; mt++) {
            const int m0 = wm + mt * 16;
            LOAD_AFRAG(ahr[mt], Ah_r, m0); LOAD_AFRAG(alr[mt], Al_r, m0);
            LOAD_AFRAG(ahi[mt], Ah_i, m0); LOAD_AFRAG(ali[mt], Al_i, m0);
            LOAD_AFRAG(ahs[mt], Ah_s, m0); LOAD_AFRAG(als[mt], Al_s, m0);
        }
        #pragma unroll
        for (int nt = 0; nt < 4; nt++) {
            const int n0 = wn + nt * 8;
            uint32_t bhr[2], blr[2], bhi[2], bli[2], bhs[2], bls[2];
            LOAD_BFRAG(bhr, Wh_r, n0); LOAD_BFRAG(blr, Wl_r, n0);
            LOAD_BFRAG(bhi, Wh_i, n0); LOAD_BFRAG(bli, Wl_i, n0);
            LOAD_BFRAG(bhs, Wh_s, n0); LOAD_BFRAG(bls, Wl_s, n0);
            #pragma unroll
            for (int mt = 0; mt < 2; mt++) {
                MMA_BF16(t1[mt][nt], ahr[mt], bhr);
                MMA_BF16(t1[mt][nt], ahr[mt], blr);
                MMA_BF16(t1[mt][nt], alr[mt], bhr);
                MMA_BF16(t2[mt][nt], ahi[mt], bhi);
                MMA_BF16(t2[mt][nt], ahi[mt], bli);
                MMA_BF16(t2[mt][nt], ali[mt], bhi);
                MMA_BF16(t3[mt][nt], ahs[mt], bhs);
                MMA_BF16(t3[mt][nt], ahs[mt], bls);
                MMA_BF16(t3[mt][nt], als[mt], bhs);
            }
        }
        __syncthreads();
    }
    // epilogue: cr = t1 - t2, ci = t3 - t1 - t2
    #pragma unroll
    for (int mt = 0; mt < 2; mt++)
        #pragma unroll
        for (int nt = 0; nt < 4; nt++)
            #pragma unroll
            for (int e = 0; e < 4; e++) {
                const int m = bm + wm + mt * 16 + g + ((e >> 1) ? 8 : 0);
                const int n = bn + wn + nt * 8 + tg * 2 + (e & 1);
                float vr = t1[mt][nt][e] - t2[mt][nt][e];
                float vi = t3[mt][nt][e] - t1[mt][nt][e] - t2[mt][nt][e];
                if (br) { vr += br[n]; vi += bi[n]; }
                if (flags & 2) { vr = gelu_f(vr); vi = gelu_f(vi); }
                const size_t o = (size_t)m * Nn + n;
                if (flags & 1) { vr += Rr[o]; vi += Ri[o]; }
                Cr[o] = vr; Ci[o] = vi;
            }
}

// ====================================================================================
// bf16-split scores: S[b,h,i,j] = 0.125 * (Qr.Kr + Qi.Ki) over dh=64
// ====================================================================================
__global__ __launch_bounds__(256, 1) void qk_tc(
    const float* __restrict__ Qr, const float* __restrict__ Qi,
    const float* __restrict__ Kr, const float* __restrict__ Ki,
    float* __restrict__ S)
{
    __shared__ uint32_t Ah_r[8][136], Al_r[8][136], Ah_i[8][136], Al_i[8][136];
    __shared__ uint32_t Wh_r[8][72],  Wl_r[8][72],  Wh_i[8][72],  Wl_i[8][72];
    const int bh = blockIdx.z;
    const int b = bh >> 4, h = bh & 15;
    const size_t xb = (size_t)b * SEQ * DIMSZ + h * DHEAD;
    const float* qr = Qr + xb; const float* qi = Qi + xb;
    const float* kr = Kr + xb; const float* ki = Ki + xb;
    float* s = S + (size_t)bh * SEQ * SEQ;
    const int bm = blockIdx.y * 128, bn = blockIdx.x * 64;
    const int tid = threadIdx.x;
    const int warp = tid >> 5, lane = tid & 31;
    const int wm = (warp >> 1) * 32, wn = (warp & 1) * 32;
    const int g = lane >> 2, tg = lane & 3;
    const int arow = tid >> 2;
    const int kseg = (tid & 3) * 4;
    const int p0 = (tid & 3) * 2;

    float acc[2][4][4];
    #pragma unroll
    for (int mt = 0; mt < 2; mt++)
        #pragma unroll
        for (int nt = 0; nt < 4; nt++)
            #pragma unroll
            for (int e = 0; e < 4; e++) acc[mt][nt][e] = 0.f;

    #pragma unroll
    for (int k0 = 0; k0 < DHEAD; k0 += 16) {
        #pragma unroll
        for (int r = 0; r < 2; r++) {
            const int row = arow + r * 64;
            const float4 vr4 = *(const float4*)&qr[(size_t)(bm + row) * DIMSZ + k0 + kseg];
            const float4 vi4 = *(const float4*)&qi[(size_t)(bm + row) * DIMSZ + k0 + kseg];
            split2(vr4.x, vr4.y, Ah_r[p0][row],     Al_r[p0][row]);
            split2(vr4.z, vr4.w, Ah_r[p0 + 1][row], Al_r[p0 + 1][row]);
            split2(vi4.x, vi4.y, Ah_i[p0][row],     Al_i[p0][row]);
            split2(vi4.z, vi4.w, Ah_i[p0 + 1][row], Al_i[p0 + 1][row]);
        }
        {
            const float4 vr4 = *(const float4*)&kr[(size_t)(bn + arow) * DIMSZ + k0 + kseg];
            const float4 vi4 = *(const float4*)&ki[(size_t)(bn + arow) * DIMSZ + k0 + kseg];
            split2(vr4.x, vr4.y, Wh_r[p0][arow],     Wl_r[p0][arow]);
            split2(vr4.z, vr4.w, Wh_r[p0 + 1][arow], Wl_r[p0 + 1][arow]);
            split2(vi4.x, vi4.y, Wh_i[p0][arow],     Wl_i[p0][arow]);
            split2(vi4.z, vi4.w, Wh_i[p0 + 1][arow], Wl_i[p0 + 1][arow]);
        }
        __syncthreads();

        uint32_t ahr[2][4], alr[2][4], ahi[2][4], ali[2][4];
        #pragma unroll
        for (int mt = 0; mt < 2; mt++) {
            const int m0 = wm + mt * 16;
            LOAD_AFRAG(ahr[mt], Ah_r, m0); LOAD_AFRAG(alr[mt], Al_r, m0);
            LOAD_AFRAG(ahi[mt], Ah_i, m0); LOAD_AFRAG(ali[mt], Al_i, m0);
        }
        #pragma unroll
        for (int nt = 0; nt < 4; nt++) {
            const int n0 = wn + nt * 8;
            uint32_t bhr[2], blr[2], bhi[2], bli[2];
            LOAD_BFRAG(bhr, Wh_r, n0); LOAD_BFRAG(blr, Wl_r, n0);
            LOAD_BFRAG(bhi, Wh_i, n0); LOAD_BFRAG(bli, Wl_i, n0);
            #pragma unroll
            for (int mt = 0; mt < 2; mt++) {
                MMA_BF16(acc[mt][nt], ahr[mt], bhr);
                MMA_BF16(acc[mt][nt], ahr[mt], blr);
                MMA_BF16(acc[mt][nt], alr[mt], bhr);
                MMA_BF16(acc[mt][nt], ahi[mt], bhi);
                MMA_BF16(acc[mt][nt], ahi[mt], bli);
                MMA_BF16(acc[mt][nt], ali[mt], bhi);
            }
        }
        __syncthreads();
    }
    #pragma unroll
    for (int mt = 0; mt < 2; mt++)
        #pragma unroll
        for (int nt = 0; nt < 4; nt++)
            #pragma unroll
            for (int e = 0; e < 4; e++) {
                const int m = bm + wm + mt * 16 + g + ((e >> 1) ? 8 : 0);
                const int n = bn + wn + nt * 8 + tg * 2 + (e & 1);
                s[(size_t)m * SEQ + n] = acc[mt][nt][e] * 0.125f;
            }
}

// ====================================================================================
// bf16-split out_f = attn @ Vf, register-prefetch pipelined
// ====================================================================================
__global__ __launch_bounds__(256, 1) void av_tc(
    const float* __restrict__ S, const float* __restrict__ Vr, const float* __restrict__ Vi,
    float* __restrict__ Or, float* __restrict__ Oi)
{
    __shared__ uint32_t Ah[8][136], Al[8][136];
    __shared__ uint32_t Vh_r[8][72], Vl_r[8][72], Vh_i[8][72], Vl_i[8][72];
    const int bh = blockIdx.z;
    const int b = bh >> 4, h = bh & 15;
    const float* a = S + (size_t)bh * SEQ * SEQ;
    const size_t vb = (size_t)b * SEQ * DIMSZ + h * DHEAD;
    const float* vr = Vr + vb; const float* vi = Vi + vb;
    float* outr = Or + vb; float* outi = Oi + vb;
    const int bm = blockIdx.x * 128;
    const int tid = threadIdx.x;
    const int warp = tid >> 5, lane = tid & 31;
    const int wm = (warp >> 1) * 32, wn = (warp & 1) * 32;
    const int g = lane >> 2, tg = lane & 3;
    const int arow = tid >> 2;
    const int kseg = (tid & 3) * 4;
    const int p0 = (tid & 3) * 2;
    const int vp = tid >> 5;              // 0..7
    const int vn = (tid & 31) * 2;        // 0..62

    const float* pa0 = &a[(size_t)(bm + arow) * SEQ + kseg];
    const float* pa1 = &a[(size_t)(bm + arow + 64) * SEQ + kseg];
    const float* pvr0 = &vr[(size_t)(2 * vp) * DIMSZ + vn];
    const float* pvr1 = &vr[(size_t)(2 * vp + 1) * DIMSZ + vn];
    const float* pvi0 = &vi[(size_t)(2 * vp) * DIMSZ + vn];
    const float* pvi1 = &vi[(size_t)(2 * vp + 1) * DIMSZ + vn];

    float or_[2][4][4], oi_[2][4][4];
    #pragma unroll
    for (int mt = 0; mt < 2; mt++)
        #pragma unroll
        for (int nt = 0; nt < 4; nt++)
            #pragma unroll
            for (int e = 0; e < 4; e++) { or_[mt][nt][e] = 0.f; oi_[mt][nt][e] = 0.f; }

    float4 fA[2];
    float2 fr0, fr1, fi0, fi1;
    fA[0] = *(const float4*)pa0; fA[1] = *(const float4*)pa1;
    fr0 = *(const float2*)pvr0; fr1 = *(const float2*)pvr1;
    fi0 = *(const float2*)pvi0; fi1 = *(const float2*)pvi1;

    for (int k0 = 0; k0 < SEQ; k0 += 16) {
        #pragma unroll
        for (int r = 0; r < 2; r++) {
            const int row = arow + r * 64;
            split2(fA[r].x, fA[r].y, Ah[p0][row],     Al[p0][row]);
            split2(fA[r].z, fA[r].w, Ah[p0 + 1][row], Al[p0 + 1][row]);
        }
        split2(fr0.x, fr1.x, Vh_r[vp][vn],     Vl_r[vp][vn]);
        split2(fr0.y, fr1.y, Vh_r[vp][vn + 1], Vl_r[vp][vn + 1]);
        split2(fi0.x, fi1.x, Vh_i[vp][vn],     Vl_i[vp][vn]);
        split2(fi0.y, fi1.y, Vh_i[vp][vn + 1], Vl_i[vp][vn + 1]);
        __syncthreads();

        if (k0 + 16 < SEQ) {
            const int kn = k0 + 16;
            fA[0] = *(const float4*)(pa0 + kn); fA[1] = *(const float4*)(pa1 + kn);
            const size_t vo = (size_t)kn * DIMSZ;
            fr0 = *(const float2*)(pvr0 + vo); fr1 = *(const float2*)(pvr1 + vo);
            fi0 = *(const float2*)(pvi0 + vo); fi1 = *(const float2*)(pvi1 + vo);
        }

        uint32_t ah[2][4], al[2][4];
        #pragma unroll
        for (int mt = 0; mt < 2; mt++) {
            const int m0 = wm + mt * 16;
            LOAD_AFRAG(ah[mt], Ah, m0); LOAD_AFRAG(al[mt], Al, m0);
        }
        #pragma unroll
        for (int nt = 0; nt < 4; nt++) {
            const int n0 = wn + nt * 8;
            uint32_t bhr[2], blr[2], bhi[2], bli[2];
            LOAD_BFRAG(bhr, Vh_r, n0); LOAD_BFRAG(blr, Vl_r, n0);
            LOAD_BFRAG(bhi, Vh_i, n0); LOAD_BFRAG(bli, Vl_i, n0);
            #pragma unroll
            for (int mt = 0; mt < 2; mt++) {
                MMA_BF16(or_[mt][nt], ah[mt], bhr);
                MMA_BF16(or_[mt][nt], ah[mt], blr);
                MMA_BF16(or_[mt][nt], al[mt], bhr);
                MMA_BF16(oi_[mt][nt], ah[mt], bhi);
                MMA_BF16(oi_[mt][nt], ah[mt], bli);
                MMA_BF16(oi_[mt][nt], al[mt], bhi);
            }
        }
        __syncthreads();
    }
    #pragma unroll
    for (int mt = 0; mt < 2; mt++)
        #pragma unroll
        for (int nt = 0; nt < 4; nt++)
            #pragma unroll
            for (int e = 0; e < 4; e++) {
                const int m = bm + wm + mt * 16 + g + ((e >> 1) ? 8 : 0);
                const int n = wn + nt * 8 + tg * 2 + (e & 1);
                const size_t o = (size_t)m * DIMSZ + n;
                outr[o] = or_[mt][nt][e];
                outi[o] = oi_[mt][nt][e];
            }
}

// ---------------- real GEMM (1024^3): C = scl*(A @ B) + alpha*I ----------------
__global__ __launch_bounds__(256) void rgemm_kernel(
    const float* __restrict__ A, const float* __restrict__ Bm,
    float* __restrict__ C, float scl, float alpha)
{
    __shared__ float As[16][68], Bs[16][68];
    const int bm = blockIdx.y * 64, bn = blockIdx.x * 64;
    const int tid = threadIdx.x;
    const int tx = tid & 15, ty = tid >> 4;
    float acc[4][4] = {{0.f}};
    for (int k0 = 0; k0 < DIMSZ; k0 += 16) {
        #pragma unroll
        for (int i = 0; i < 4; i++) {
            int idx = tid + i * 256;
            int m = idx >> 4, kk = idx & 15;
            As[kk][m] = A[(size_t)(bm + m) * DIMSZ + k0 + kk];
            int n = idx & 63, k2 = idx >> 6;
            Bs[k2][n] = Bm[(size_t)(k0 + k2) * DIMSZ + bn + n];
        }
        __syncthreads();
        #pragma unroll
        for (int kk = 0; kk < 16; kk++) {
            float4 a4 = *(const float4*)&As[kk][ty * 4];
            float4 b4 = *(const float4*)&Bs[kk][tx * 4];
            float a[4] = {a4.x, a4.y, a4.z, a4.w};
            float b[4] = {b4.x, b4.y, b4.z, b4.w};
            #pragma unroll
            for (int i = 0; i < 4; i++)
                #pragma unroll
                for (int j = 0; j < 4; j++)
                    acc[i][j] += a[i] * b[j];
        }
        __syncthreads();
    }
    #pragma unroll
    for (int i = 0; i < 4; i++)
        #pragma unroll
        for (int j = 0; j < 4; j++) {
            int m = bm + ty * 4 + i, n = bn + tx * 4 + j;
            C[(size_t)m * DIMSZ + n] = scl * acc[i][j] + ((m == n) ? alpha : 0.f);
        }
}

// ---------------- FFT along seq axis (smem twiddle table) ----------------
__global__ __launch_bounds__(256) void fft_kernel(float* __restrict__ re, float* __restrict__ im,
                                                  int inv, float scale)
{
    __shared__ float sr[SEQ * 4], si[SEQ * 4];
    __shared__ float twr[512], twi[512];
    const int c0 = blockIdx.x * 4;
    const int b = blockIdx.y;
    const size_t base = (size_t)b * SEQ * DIMSZ;
    const int tid = threadIdx.x;
    const float sgn = inv ? 1.0f : -1.0f;

    // twiddle table: twr/twi[j] = exp(i*2*pi*j/1024), j=0..511
    #pragma unroll
    for (int j = tid; j < 512; j += 256) {
        float ang = 6.283185307179586f * (float)j * (1.0f / 1024.0f);
        float s, c;
        sincosf(ang, &s, &c);
        twr[j] = c; twi[j] = s;
    }

    for (int i = tid; i < SEQ * 4; i += 256) {
        int n = i >> 2, c = i & 3;
        int rn = __brev((unsigned)n) >> 22;
        size_t g = base + (size_t)n * DIMSZ + c0 + c;
        sr[rn * 4 + c] = re[g];
        si[rn * 4 + c] = im[g];
    }
    __syncthreads();

    for (int s = 1; s <= 10; s++) {
        int half = 1 << (s - 1);
        int shift = 10 - s;
        for (int i = tid; i < 2048; i += 256) {
            int j = i >> 2, c = i & 3;
            int k = j & (half - 1);
            int grp = j >> (s - 1);
            int i0 = ((grp << s) + k) * 4 + c;
            int i1 = i0 + half * 4;
            int tw = k << shift;
            float cw = twr[tw];
            float sw = sgn * twi[tw];
            float ur = sr[i0], ui = si[i0];
            float vr = sr[i1], vi = si[i1];
            float tr = vr * cw - vi * sw;
            float ti = vr * sw + vi * cw;
            sr[i0] = ur + tr; si[i0] = ui + ti;
            sr[i1] = ur - tr; si[i1] = ui - ti;
        }
        __syncthreads();
    }

    for (int i = tid; i < SEQ * 4; i += 256) {
        int n = i >> 2, c = i & 3;
        size_t g = base + (size_t)n * DIMSZ + c0 + c;
        re[g] = sr[n * 4 + c] * scale;
        im[g] = si[n * 4 + c] * scale;
    }
}

// ---------------- softmax over last dim (1024) ----------------
__global__ __launch_bounds__(256) void softmax_kernel(float* __restrict__ S)
{
    float* row = S + (size_t)blockIdx.x * SEQ;
    const int t = threadIdx.x;
    __shared__ float red[256];
    float4 v = *(float4*)&row[t * 4];
    float m = fmaxf(fmaxf(v.x, v.y), fmaxf(v.z, v.w));
    red[t] = m; __syncthreads();
    for (int s = 128; s > 0; s >>= 1) {
        if (t < s) red[t] = fmaxf(red[t], red[t + s]);
        __syncthreads();
    }
    m = red[0]; __syncthreads();
    v.x = expf(v.x - m); v.y = expf(v.y - m);
    v.z = expf(v.z - m); v.w = expf(v.w - m);
    float sum = v.x + v.y + v.z + v.w;
    red[t] = sum; __syncthreads();
    for (int s = 128; s > 0; s >>= 1) {
        if (t < s) red[t] += red[t + s];
        __syncthreads();
    }
    float inv = 1.0f / red[0];
    v.x *= inv; v.y *= inv; v.z *= inv; v.w *= inv;
    *(float4*)&row[t * 4] = v;
}

// ---------------- small elementwise kernels ----------------
__global__ __launch_bounds__(256) void scaleH_kernel(const float* __restrict__ H,
                                                     const float* __restrict__ dt,
                                                     float* __restrict__ M)
{
    int i = blockIdx.x * 256 + threadIdx.x;
    M[i] = H[i] * dt[0];
}

__global__ __launch_bounds__(256) void axpbI_kernel(const float* __restrict__ P,
                                                    float a, float b, float* __restrict__ T)
{
    int i = blockIdx.x * 256 + threadIdx.x;
    float v = a * P[i];
    int r = i >> 10, c = i & 1023;
    if (r == c) v += b;
    T[i] = v;
}

// ---------------- host launch ----------------
static float* symaddr(const void* sym)
{
    void* p = nullptr;
    cudaGetSymbolAddress(&p, sym);
    return (float*)p;
}

extern "C" void kernel_launch(void* const* d_in, const int* in_sizes, int n_in,
                              void* d_out, int out_size)
{
    const float* xr = (const float*)d_in[0];
    const float* xi = (const float*)d_in[1];
    const float* Wr_q = (const float*)d_in[2];  const float* Wi_q = (const float*)d_in[3];
    const float* br_q = (const float*)d_in[4];  const float* bi_q = (const float*)d_in[5];
    const float* Wr_k = (const float*)d_in[6];  const float* Wi_k = (const float*)d_in[7];
    const float* br_k = (const float*)d_in[8];  const float* bi_k = (const float*)d_in[9];
    const float* Wr_v = (const float*)d_in[10]; const float* Wi_v = (const float*)d_in[11];
    const float* br_v = (const float*)d_in[12]; const float* bi_v = (const float*)d_in[13];
    const float* Wr_o = (const float*)d_in[14]; const float* Wi_o = (const float*)d_in[15];
    const float* br_o = (const float*)d_in[16]; const float* bi_o = (const float*)d_in[17];
    const float* Wr_f1 = (const float*)d_in[18]; const float* Wi_f1 = (const float*)d_in[19];
    const float* br_f1 = (const float*)d_in[20]; const float* bi_f1 = (const float*)d_in[21];
    const float* Wr_f2 = (const float*)d_in[22]; const float* Wi_f2 = (const float*)d_in[23];
    const float* br_f2 = (const float*)d_in[24]; const float* bi_f2 = (const float*)d_in[25];
    const float* Hm = (const float*)d_in[26];
    const float* dt = (const float*)d_in[27];

    float* Qr = symaddr(g_Qr);   float* Qi = symaddr(g_Qi);
    float* Kr = symaddr(g_Kr);   float* Ki = symaddr(g_Ki);
    float* Vr = symaddr(g_Vr);   float* Vi = symaddr(g_Vi);
    float* Sb = symaddr(g_S);
    float* OFr = symaddr(g_OFr); float* OFi = symaddr(g_OFi);
    float* x1r = symaddr(g_x1r); float* x1i = symaddr(g_x1i);
    float* x2r = symaddr(g_x2r); float* x2i = symaddr(g_x2i);
    float* hr = symaddr(g_hr);   float* hi = symaddr(g_hi);
    float* Mx = symaddr(g_Mx);   float* P2 = symaddr(g_P2);
    float* T1 = symaddr(g_T1);   float* T2 = symaddr(g_T2);
    float* Uc = symaddr(g_Ucos); float* Us = symaddr(g_UsinN);

    dim3 blk(256);
    dim3 gP(DIMSZ / 64, MROWS / 128);      // (16, 16)
    dim3 gF(DIMSZ / 4, BATCH);             // (256, 2)
    dim3 gS(SEQ / 64, SEQ / 128, BATCH * HEADS);   // (16, 8, 32)
    dim3 gA(SEQ / 128, 1, BATCH * HEADS);          // (8, 1, 32)
    dim3 gR(DIMSZ / 64, DIMSZ / 64);       // (16, 16)
    dim3 gF1(HIDDEN / 64, MROWS / 128);    // (64, 16)

    // --- QKV projections (tensor core, bf16-split + Karatsuba) ---
    cgemm_tc<<<gP, blk>>>(xr, xi, Wr_q, Wi_q, br_q, bi_q, nullptr, nullptr,
                          Qr, Qi, DIMSZ, DIMSZ, 0);
    cgemm_tc<<<gP, blk>>>(xr, xi, Wr_k, Wi_k, br_k, bi_k, nullptr, nullptr,
                          Kr, Ki, DIMSZ, DIMSZ, 0);
    cgemm_tc<<<gP, blk>>>(xr, xi, Wr_v, Wi_v, br_v, bi_v, nullptr, nullptr,
                          Vr, Vi, DIMSZ, DIMSZ, 0);

    // --- FFTs along sequence ---
    fft_kernel<<<gF, blk>>>(Qr, Qi, 0, 1.0f);
    fft_kernel<<<gF, blk>>>(Kr, Ki, 0, 1.0f);
    fft_kernel<<<gF, blk>>>(Vr, Vi, 0, 1.0f);

    // --- attention ---
    qk_tc<<<gS, blk>>>(Qr, Qi, Kr, Ki, Sb);
    softmax_kernel<<<BATCH * HEADS * SEQ, blk>>>(Sb);
    av_tc<<<gA, blk>>>(Sb, Vr, Vi, OFr, OFi);
    fft_kernel<<<gF, blk>>>(OFr, OFi, 1, 1.0f / (float)SEQ);

    // --- O projection + residual ---
    cgemm_tc<<<gP, blk>>>(OFr, OFi, Wr_o, Wi_o, br_o, bi_o, xr, xi,
                          x1r, x1i, DIMSZ, DIMSZ, 1);

    // --- FFN ---
    cgemm_tc<<<gF1, blk>>>(x1r, x1i, Wr_f1, Wi_f1, br_f1, bi_f1, nullptr, nullptr,
                           hr, hi, HIDDEN, DIMSZ, 2);
    cgemm_tc<<<gP, blk>>>(hr, hi, Wr_f2, Wi_f2, br_f2, bi_f2, x1r, x1i,
                          x2r, x2i, DIMSZ, HIDDEN, 1);

    // --- U = expm(-i H dt) = cos(dtH) - i sin(dtH), via Taylor/Horner in P2=(dtH)^2 ---
    scaleH_kernel<<<DIMSZ * DIMSZ / 256, blk>>>(Hm, dt, Mx);
    rgemm_kernel<<<gR, blk>>>(Mx, Mx, P2, 1.0f, 0.0f);
    axpbI_kernel<<<DIMSZ * DIMSZ / 256, blk>>>(P2, -1.0f / 720.0f, 1.0f / 24.0f, T1);
    rgemm_kernel<<<gR, blk>>>(T1, P2, T2, 1.0f, -0.5f);
    rgemm_kernel<<<gR, blk>>>(T2, P2, Uc, 1.0f, 1.0f);
    axpbI_kernel<<<DIMSZ * DIMSZ / 256, blk>>>(P2, -1.0f / 5040.0f, 1.0f / 120.0f, T1);
    rgemm_kernel<<<gR, blk>>>(T1, P2, T2, 1.0f, -1.0f / 6.0f);
    rgemm_kernel<<<gR, blk>>>(T2, P2, T1, 1.0f, 1.0f);
    rgemm_kernel<<<gR, blk>>>(Mx, T1, Us, -1.0f, 0.0f);   // Us = -sin(dtH)

    // --- final: out = x2 @ U; U symmetric so U == U^T, reuse complex GEMM ---
    float* outR = (float*)d_out;
    float* outI = outR + (size_t)MROWS * DIMSZ;
    cgemm_tc<<<gP, blk>>>(x2r, x2i, Uc, Us, nullptr, nullptr, nullptr, nullptr,
                          outR, outI, DIMSZ, DIMSZ, 0);
}

// round 17
// speedup vs baseline: 1.9287x; 1.1620x over previous
#include <cuda_runtime.h>
#include <cuda_bf16.h>
#include <math.h>
#include <stdint.h>

#define DIMSZ 1024
#define BATCH 2
#define SEQ 1024
#define HEADS 16
#define DHEAD 64
#define HIDDEN 4096
#define MROWS (BATCH*SEQ)          /* 2048 */
#define BND (MROWS*DIMSZ)          /* 2097152 */

// ---------------- fp32 scratch ----------------
__device__ float g_Qr[BND], g_Qi[BND];
__device__ float g_Kr[BND], g_Ki[BND];
__device__ float g_Vr[BND], g_Vi[BND];
__device__ float g_S[(size_t)BATCH*HEADS*SEQ*SEQ];
__device__ float g_OFr[BND], g_OFi[BND];
__device__ float g_x1r[BND], g_x1i[BND];
__device__ float g_x2r[BND], g_x2i[BND];
__device__ float g_hr[MROWS*HIDDEN], g_hi[MROWS*HIDDEN];
__device__ float g_Mx[DIMSZ*DIMSZ], g_P2[DIMSZ*DIMSZ];
__device__ float g_T1[DIMSZ*DIMSZ], g_T2[DIMSZ*DIMSZ];
__device__ float g_Ucos[DIMSZ*DIMSZ], g_UsinN[DIMSZ*DIMSZ];

// ---------------- packed bf16 hi/lo planes (k-pair packed uint32) ----------------
// 6-plane order: 0=Hr 1=Lr 2=Hi 3=Li 4=Hs 5=Ls ; 4-plane: Hr Lr Hi Li ; 2-plane: H L
__device__ uint32_t g_pX [6u*2048*512];
__device__ uint32_t g_pOF[6u*2048*512];
__device__ uint32_t g_pX1[6u*2048*512];
__device__ uint32_t g_pX2[6u*2048*512];
__device__ uint32_t g_pH [6u*2048*2048];
__device__ uint32_t g_pWq[6u*1024*512], g_pWk[6u*1024*512];
__device__ uint32_t g_pWv[6u*1024*512], g_pWo[6u*1024*512];
__device__ uint32_t g_pF1[6u*4096*512], g_pF2[6u*1024*2048];
__device__ uint32_t g_pU [6u*1024*512];
__device__ uint32_t g_pQ [4u*2048*512], g_pK[4u*2048*512], g_pV[4u*2048*512];
__device__ uint32_t g_pS [2ull*32768*512];

__device__ __forceinline__ float gelu_f(float x) {
    return 0.5f * x * (1.0f + erff(x * 0.70710678118654752440f));
}

__device__ __forceinline__ void split2(float f0, float f1, uint32_t& hi, uint32_t& lo) {
    __nv_bfloat16 h0 = __float2bfloat16_rn(f0);
    __nv_bfloat16 h1 = __float2bfloat16_rn(f1);
    float r0 = f0 - __bfloat162float(h0);
    float r1 = f1 - __bfloat162float(h1);
    __nv_bfloat16 l0 = __float2bfloat16_rn(r0);
    __nv_bfloat16 l1 = __float2bfloat16_rn(r1);
    hi = (uint32_t)__bfloat16_as_ushort(h0) | ((uint32_t)__bfloat16_as_ushort(h1) << 16);
    lo = (uint32_t)__bfloat16_as_ushort(l0) | ((uint32_t)__bfloat16_as_ushort(l1) << 16);
}

#define MMA_BF16(d, a, b) \
    asm volatile("mma.sync.aligned.m16n8k16.row.col.f32.bf16.bf16.f32 " \
        "{%0,%1,%2,%3}, {%4,%5,%6,%7}, {%8,%9}, {%0,%1,%2,%3};" \
        : "+f"(d[0]), "+f"(d[1]), "+f"(d[2]), "+f"(d[3]) \
        : "r"(a[0]), "r"(a[1]), "r"(a[2]), "r"(a[3]), "r"(b[0]), "r"(b[1]))

__device__ __forceinline__ void cp16(uint32_t dst, const void* src) {
    asm volatile("cp.async.ca.shared.global [%0], [%1], 16;" :: "r"(dst), "l"(src));
}
#define CP_COMMIT() asm volatile("cp.async.commit_group;")
#define CP_WAIT0()  asm volatile("cp.async.wait_group 0;")
#define CP_WAIT1()  asm volatile("cp.async.wait_group 1;")

// pack fp32 (R,I) row-major [rows][K] into 6 planes of k-pair packed words.
__global__ __launch_bounds__(256) void pack6_kernel(
    const float* __restrict__ R, const float* __restrict__ I,
    uint32_t* __restrict__ out, size_t total)
{
    size_t p = (size_t)blockIdx.x * 256 + threadIdx.x;
    if (p >= total) return;
    float f0 = R[2*p], f1 = R[2*p+1];
    float g0 = I[2*p], g1 = I[2*p+1];
    uint32_t h, l;
    split2(f0, f1, h, l); out[p] = h; out[total + p] = l;
    split2(g0, g1, h, l); out[2*total + p] = h; out[3*total + p] = l;
    split2(f0+g0, f1+g1, h, l); out[4*total + p] = h; out[5*total + p] = l;
}

// ====================================================================================
// packed Karatsuba complex GEMM: C = A @ W^T (+bias)(+gelu)(+residual)
// A: 6 planes [M][K2], W: 6 planes [Nn][K2]. Block 128x64, 8 warps 32x32, BK=32.
// cp.async double-buffered. Dynamic smem = 184320 B.
// ====================================================================================
#define CG_A_PL 2560            /* 128*20 */
#define CG_W_PL 1280            /* 64*20 */
#define CG_ABUF 15360           /* 6*2560 */
#define CG_BUF  23040           /* ABUF + 6*1280 */
#define CG_SMEM (2*CG_BUF*4)

__global__ __launch_bounds__(256, 1) void cgemm_tc(
    const uint32_t* __restrict__ Ap, const uint32_t* __restrict__ Wp,
    size_t APS, size_t WPS,
    const float* __restrict__ br, const float* __restrict__ bi,
    const float* __restrict__ Rr, const float* __restrict__ Ri,
    float* __restrict__ Cr, float* __restrict__ Ci,
    int Nn, int K, int flags)
{
    extern __shared__ uint32_t dsm[];
    const uint32_t sbase = (uint32_t)__cvta_generic_to_shared(dsm);
    const int K2 = K >> 1;
    const int bm = blockIdx.y * 128, bn = blockIdx.x * 64;
    const int tid = threadIdx.x;
    const int warp = tid >> 5, lane = tid & 31;
    const int wm = (warp >> 1) * 32, wn = (warp & 1) * 32;
    const int g = lane >> 2, tg = lane & 3;

    float t1[2][4][4], t2[2][4][4], t3[2][4][4];
    #pragma unroll
    for (int mt = 0; mt < 2; mt++)
        #pragma unroll
        for (int nt = 0; nt < 4; nt++)
            #pragma unroll
            for (int e = 0; e < 4; e++) { t1[mt][nt][e]=0.f; t2[mt][nt][e]=0.f; t3[mt][nt][e]=0.f; }

    // stage copy lambda: 16 pairs per stage (BK=32); A 3072 chunks, W 1536 chunks
    auto stage = [&](int buf, int kp) {
        const uint32_t ab = sbase + (uint32_t)(buf * CG_BUF) * 4;
        const uint32_t wb = ab + CG_ABUF * 4;
        #pragma unroll
        for (int j = 0; j < 12; j++) {
            int id = tid + j * 256;
            int plane = id >> 9, rem = id & 511;
            int row = rem >> 2, half = rem & 3;
            const uint32_t* src = Ap + (size_t)plane * APS + (size_t)(bm + row) * K2 + kp + half * 4;
            cp16(ab + (uint32_t)(plane * CG_A_PL + row * 20 + half * 4) * 4, src);
        }
        #pragma unroll
        for (int j = 0; j < 6; j++) {
            int id = tid + j * 256;
            int plane = id >> 8, rem = id & 255;
            int row = rem >> 2, half = rem & 3;
            const uint32_t* src = Wp + (size_t)plane * WPS + (size_t)(bn + row) * K2 + kp + half * 4;
            cp16(wb + (uint32_t)(plane * CG_W_PL + row * 20 + half * 4) * 4, src);
        }
    };

    const int NS = K >> 5;
    stage(0, 0); CP_COMMIT();

    for (int s = 0; s < NS; s++) {
        const int cur = s & 1;
        if (s + 1 < NS) { stage(cur ^ 1, (s + 1) * 16); CP_COMMIT(); CP_WAIT1(); }
        else { CP_WAIT0(); }
        __syncthreads();

        const uint32_t* Bp = dsm + cur * CG_BUF;
        const uint32_t* Wb = Bp + CG_ABUF;
        #pragma unroll
        for (int ks = 0; ks < 2; ks++) {
            const int kb = ks * 8;
            uint32_t ahr[2][4], alr[2][4], ahi[2][4], ali[2][4], ahs[2][4], als[2][4];
            #pragma unroll
            for (int mt = 0; mt < 2; mt++) {
                const int r0 = (wm + mt * 16 + g) * 20 + kb + tg;
                const int r1 = r0 + 160; /* +8 rows */
                ahr[mt][0]=Bp[0*CG_A_PL+r0]; ahr[mt][1]=Bp[0*CG_A_PL+r1];
                ahr[mt][2]=Bp[0*CG_A_PL+r0+4]; ahr[mt][3]=Bp[0*CG_A_PL+r1+4];
                alr[mt][0]=Bp[1*CG_A_PL+r0]; alr[mt][1]=Bp[1*CG_A_PL+r1];
                alr[mt][2]=Bp[1*CG_A_PL+r0+4]; alr[mt][3]=Bp[1*CG_A_PL+r1+4];
                ahi[mt][0]=Bp[2*CG_A_PL+r0]; ahi[mt][1]=Bp[2*CG_A_PL+r1];
                ahi[mt][2]=Bp[2*CG_A_PL+r0+4]; ahi[mt][3]=Bp[2*CG_A_PL+r1+4];
                ali[mt][0]=Bp[3*CG_A_PL+r0]; ali[mt][1]=Bp[3*CG_A_PL+r1];
                ali[mt][2]=Bp[3*CG_A_PL+r0+4]; ali[mt][3]=Bp[3*CG_A_PL+r1+4];
                ahs[mt][0]=Bp[4*CG_A_PL+r0]; ahs[mt][1]=Bp[4*CG_A_PL+r1];
                ahs[mt][2]=Bp[4*CG_A_PL+r0+4]; ahs[mt][3]=Bp[4*CG_A_PL+r1+4];
                als[mt][0]=Bp[5*CG_A_PL+r0]; als[mt][1]=Bp[5*CG_A_PL+r1];
                als[mt][2]=Bp[5*CG_A_PL+r0+4]; als[mt][3]=Bp[5*CG_A_PL+r1+4];
            }
            #pragma unroll
            for (int nt = 0; nt < 4; nt++) {
                const int c0 = (wn + nt * 8 + g) * 20 + kb + tg;
                uint32_t bhr[2], blr[2], bhi[2], bli[2], bhs[2], bls[2];
                bhr[0]=Wb[0*CG_W_PL+c0]; bhr[1]=Wb[0*CG_W_PL+c0+4];
                blr[0]=Wb[1*CG_W_PL+c0]; blr[1]=Wb[1*CG_W_PL+c0+4];
                bhi[0]=Wb[2*CG_W_PL+c0]; bhi[1]=Wb[2*CG_W_PL+c0+4];
                bli[0]=Wb[3*CG_W_PL+c0]; bli[1]=Wb[3*CG_W_PL+c0+4];
                bhs[0]=Wb[4*CG_W_PL+c0]; bhs[1]=Wb[4*CG_W_PL+c0+4];
                bls[0]=Wb[5*CG_W_PL+c0]; bls[1]=Wb[5*CG_W_PL+c0+4];
                #pragma unroll
                for (int mt = 0; mt < 2; mt++) {
                    MMA_BF16(t1[mt][nt], ahr[mt], bhr);
                    MMA_BF16(t1[mt][nt], ahr[mt], blr);
                    MMA_BF16(t1[mt][nt], alr[mt], bhr);
                    MMA_BF16(t2[mt][nt], ahi[mt], bhi);
                    MMA_BF16(t2[mt][nt], ahi[mt], bli);
                    MMA_BF16(t2[mt][nt], ali[mt], bhi);
                    MMA_BF16(t3[mt][nt], ahs[mt], bhs);
                    MMA_BF16(t3[mt][nt], ahs[mt], bls);
                    MMA_BF16(t3[mt][nt], als[mt], bhs);
                }
            }
        }
        __syncthreads();
    }
    #pragma unroll
    for (int mt = 0; mt < 2; mt++)
        #pragma unroll
        for (int nt = 0; nt < 4; nt++)
            #pragma unroll
            for (int e = 0; e < 4; e++) {
                const int m = bm + wm + mt * 16 + g + ((e >> 1) ? 8 : 0);
                const int n = bn + wn + nt * 8 + tg * 2 + (e & 1);
                float vr = t1[mt][nt][e] - t2[mt][nt][e];
                float vi = t3[mt][nt][e] - t1[mt][nt][e] - t2[mt][nt][e];
                if (br) { vr += br[n]; vi += bi[n]; }
                if (flags & 2) { vr = gelu_f(vr); vi = gelu_f(vi); }
                const size_t o = (size_t)m * Nn + n;
                if (flags & 1) { vr += Rr[o]; vi += Ri[o]; }
                Cr[o] = vr; Ci[o] = vi;
            }
}

// ====================================================================================
// packed qk: S = 0.125*(Qr.Kr + Qi.Ki), K=64. 4 planes each side, BK=16, single buffer.
// ====================================================================================
#define QK_A_PL 1536            /* 128*12 */
#define QK_W_PL 768             /* 64*12 */
#define QK_ABUF 6144            /* 4*1536 */

__global__ __launch_bounds__(256, 1) void qk_tc(
    const uint32_t* __restrict__ Qp, const uint32_t* __restrict__ Kp,
    float* __restrict__ S)
{
    __shared__ uint32_t sm[QK_ABUF + 4*QK_W_PL];
    const uint32_t sbase = (uint32_t)__cvta_generic_to_shared(sm);
    const int bh = blockIdx.z;
    const int h = bh & 15;
    float* s = S + (size_t)bh * SEQ * SEQ;
    const int bm = (bh >> 4) * SEQ + blockIdx.y * 128;   // global token row (batch folded)
    const int bmo = blockIdx.y * 128;
    const int bn = (bh >> 4) * SEQ + blockIdx.x * 64;
    const int bno = blockIdx.x * 64;
    const int tid = threadIdx.x;
    const int warp = tid >> 5, lane = tid & 31;
    const int wm = (warp >> 1) * 32, wn = (warp & 1) * 32;
    const int g = lane >> 2, tg = lane & 3;
    const size_t PS = (size_t)2048 * 512;
    const int hp = h * 32;

    float acc[2][4][4];
    #pragma unroll
    for (int mt = 0; mt < 2; mt++)
        #pragma unroll
        for (int nt = 0; nt < 4; nt++)
            #pragma unroll
            for (int e = 0; e < 4; e++) acc[mt][nt][e] = 0.f;

    #pragma unroll
    for (int st = 0; st < 4; st++) {
        const int kp = hp + st * 8;
        #pragma unroll
        for (int j = 0; j < 4; j++) {
            int id = tid + j * 256;
            int plane = id >> 8, rem = id & 255;
            int row = rem >> 1, half = rem & 1;
            cp16(sbase + (uint32_t)(plane * QK_A_PL + row * 12 + half * 4) * 4,
                 Qp + (size_t)plane * PS + (size_t)(bm + row) * 512 + kp + half * 4);
        }
        #pragma unroll
        for (int j = 0; j < 2; j++) {
            int id = tid + j * 256;
            int plane = id >> 7, rem = id & 127;
            int row = rem >> 1, half = rem & 1;
            cp16(sbase + (uint32_t)(QK_ABUF + plane * QK_W_PL + row * 12 + half * 4) * 4,
                 Kp + (size_t)plane * PS + (size_t)(bn + row) * 512 + kp + half * 4);
        }
        CP_COMMIT(); CP_WAIT0();
        __syncthreads();

        uint32_t ahr[2][4], alr[2][4], ahi[2][4], ali[2][4];
        #pragma unroll
        for (int mt = 0; mt < 2; mt++) {
            const int r0 = (wm + mt * 16 + g) * 12 + tg;
            const int r1 = r0 + 96;
            ahr[mt][0]=sm[0*QK_A_PL+r0]; ahr[mt][1]=sm[0*QK_A_PL+r1];
            ahr[mt][2]=sm[0*QK_A_PL+r0+4]; ahr[mt][3]=sm[0*QK_A_PL+r1+4];
            alr[mt][0]=sm[1*QK_A_PL+r0]; alr[mt][1]=sm[1*QK_A_PL+r1];
            alr[mt][2]=sm[1*QK_A_PL+r0+4]; alr[mt][3]=sm[1*QK_A_PL+r1+4];
            ahi[mt][0]=sm[2*QK_A_PL+r0]; ahi[mt][1]=sm[2*QK_A_PL+r1];
            ahi[mt][2]=sm[2*QK_A_PL+r0+4]; ahi[mt][3]=sm[2*QK_A_PL+r1+4];
            ali[mt][0]=sm[3*QK_A_PL+r0]; ali[mt][1]=sm[3*QK_A_PL+r1];
            ali[mt][2]=sm[3*QK_A_PL+r0+4]; ali[mt][3]=sm[3*QK_A_PL+r1+4];
        }
        #pragma unroll
        for (int nt = 0; nt < 4; nt++) {
            const int c0 = QK_ABUF + (wn + nt * 8 + g) * 12 + tg;
            uint32_t bhr[2], blr[2], bhi[2], bli[2];
            bhr[0]=sm[0*QK_W_PL+c0]; bhr[1]=sm[0*QK_W_PL+c0+4];
            blr[0]=sm[1*QK_W_PL+c0]; blr[1]=sm[1*QK_W_PL+c0+4];
            bhi[0]=sm[2*QK_W_PL+c0]; bhi[1]=sm[2*QK_W_PL+c0+4];
            bli[0]=sm[3*QK_W_PL+c0]; bli[1]=sm[3*QK_W_PL+c0+4];
            #pragma unroll
            for (int mt = 0; mt < 2; mt++) {
                MMA_BF16(acc[mt][nt], ahr[mt], bhr);
                MMA_BF16(acc[mt][nt], ahr[mt], blr);
                MMA_BF16(acc[mt][nt], alr[mt], bhr);
                MMA_BF16(acc[mt][nt], ahi[mt], bhi);
                MMA_BF16(acc[mt][nt], ahi[mt], bli);
                MMA_BF16(acc[mt][nt], ali[mt], bhi);
            }
        }
        __syncthreads();
    }
    #pragma unroll
    for (int mt = 0; mt < 2; mt++)
        #pragma unroll
        for (int nt = 0; nt < 4; nt++)
            #pragma unroll
            for (int e = 0; e < 4; e++) {
                const int m = bmo + wm + mt * 16 + g + ((e >> 1) ? 8 : 0);
                const int n = bno + wn + nt * 8 + tg * 2 + (e & 1);
                s[(size_t)m * SEQ + n] = acc[mt][nt][e] * 0.125f;
            }
}

// ====================================================================================
// packed av: out = S @ Vf. A = S (2 planes), B = V seq-paired (4 planes). BK=32, dbuf.
// ====================================================================================
#define AV_A_PL 2560            /* 128*20 */
#define AV_ABUF 5120            /* 2*2560 */
#define AV_W_PL 1280            /* 64*20 */
#define AV_BUF  10240
#define AV_SMEM (2*AV_BUF*4)

__global__ __launch_bounds__(256, 1) void av_tc(
    const uint32_t* __restrict__ Sp, const uint32_t* __restrict__ Vp,
    float* __restrict__ Or, float* __restrict__ Oi)
{
    extern __shared__ uint32_t dsm[];
    const uint32_t sbase = (uint32_t)__cvta_generic_to_shared(dsm);
    const int bh = blockIdx.z;
    const int b = bh >> 4, h = bh & 15;
    const size_t vb = (size_t)b * SEQ * DIMSZ + h * DHEAD;
    float* outr = Or + vb; float* outi = Oi + vb;
    const int bm = blockIdx.x * 128;
    const int tid = threadIdx.x;
    const int warp = tid >> 5, lane = tid & 31;
    const int wm = (warp >> 1) * 32, wn = (warp & 1) * 32;
    const int g = lane >> 2, tg = lane & 3;
    const size_t SPS = (size_t)32768 * 512;
    const size_t VPS = (size_t)2048 * 512;
    const int aRow = bh * 1024 + bm;
    const int vRow = b * DIMSZ + h * DHEAD;

    float or_[2][4][4], oi_[2][4][4];
    #pragma unroll
    for (int mt = 0; mt < 2; mt++)
        #pragma unroll
        for (int nt = 0; nt < 4; nt++)
            #pragma unroll
            for (int e = 0; e < 4; e++) { or_[mt][nt][e]=0.f; oi_[mt][nt][e]=0.f; }

    auto stage = [&](int buf, int kp) {
        const uint32_t base = sbase + (uint32_t)(buf * AV_BUF) * 4;
        #pragma unroll
        for (int j = 0; j < 4; j++) {           // A: 2 planes * 128 rows * 4 = 1024
            int id = tid + j * 256;
            int plane = id >> 9, rem = id & 511;
            int row = rem >> 2, half = rem & 3;
            cp16(base + (uint32_t)(plane * AV_A_PL + row * 20 + half * 4) * 4,
                 Sp + (size_t)plane * SPS + (size_t)(aRow + row) * 512 + kp + half * 4);
        }
        #pragma unroll
        for (int j = 0; j < 4; j++) {           // B: 4 planes * 64 rows * 4 = 1024
            int id = tid + j * 256;
            int plane = id >> 8, rem = id & 255;
            int row = rem >> 2, half = rem & 3;
            cp16(base + (uint32_t)(AV_ABUF + plane * AV_W_PL + row * 20 + half * 4) * 4,
                 Vp + (size_t)plane * VPS + (size_t)(vRow + row) * 512 + kp + half * 4);
        }
    };

    const int NS = SEQ >> 5;       // 32
    stage(0, 0); CP_COMMIT();
    for (int s = 0; s < NS; s++) {
        const int cur = s & 1;
        if (s + 1 < NS) { stage(cur ^ 1, (s + 1) * 16); CP_COMMIT(); CP_WAIT1(); }
        else { CP_WAIT0(); }
        __syncthreads();

        const uint32_t* Bp = dsm + cur * AV_BUF;
        const uint32_t* Wb = Bp + AV_ABUF;
        #pragma unroll
        for (int ks = 0; ks < 2; ks++) {
            const int kb = ks * 8;
            uint32_t ah[2][4], al[2][4];
            #pragma unroll
            for (int mt = 0; mt < 2; mt++) {
                const int r0 = (wm + mt * 16 + g) * 20 + kb + tg;
                const int r1 = r0 + 160;
                ah[mt][0]=Bp[r0]; ah[mt][1]=Bp[r1]; ah[mt][2]=Bp[r0+4]; ah[mt][3]=Bp[r1+4];
                al[mt][0]=Bp[AV_A_PL+r0]; al[mt][1]=Bp[AV_A_PL+r1];
                al[mt][2]=Bp[AV_A_PL+r0+4]; al[mt][3]=Bp[AV_A_PL+r1+4];
            }
            #pragma unroll
            for (int nt = 0; nt < 4; nt++) {
                const int c0 = (wn + nt * 8 + g) * 20 + kb + tg;
                uint32_t bhr[2], blr[2], bhi[2], bli[2];
                bhr[0]=Wb[0*AV_W_PL+c0]; bhr[1]=Wb[0*AV_W_PL+c0+4];
                blr[0]=Wb[1*AV_W_PL+c0]; blr[1]=Wb[1*AV_W_PL+c0+4];
                bhi[0]=Wb[2*AV_W_PL+c0]; bhi[1]=Wb[2*AV_W_PL+c0+4];
                bli[0]=Wb[3*AV_W_PL+c0]; bli[1]=Wb[3*AV_W_PL+c0+4];
                #pragma unroll
                for (int mt = 0; mt < 2; mt++) {
                    MMA_BF16(or_[mt][nt], ah[mt], bhr);
                    MMA_BF16(or_[mt][nt], ah[mt], blr);
                    MMA_BF16(or_[mt][nt], al[mt], bhr);
                    MMA_BF16(oi_[mt][nt], ah[mt], bhi);
                    MMA_BF16(oi_[mt][nt], ah[mt], bli);
                    MMA_BF16(oi_[mt][nt], al[mt], bhi);
                }
            }
        }
        __syncthreads();
    }
    #pragma unroll
    for (int mt = 0; mt < 2; mt++)
        #pragma unroll
        for (int nt = 0; nt < 4; nt++)
            #pragma unroll
            for (int e = 0; e < 4; e++) {
                const int m = bm + wm + mt * 16 + g + ((e >> 1) ? 8 : 0);
                const int n = wn + nt * 8 + tg * 2 + (e & 1);
                const size_t o = (size_t)m * DIMSZ + n;
                outr[o] = or_[mt][nt][e];
                outi[o] = oi_[mt][nt][e];
            }
}

// ---------------- real GEMM (1024^3): C = scl*(A @ B) + alpha*I ----------------
__global__ __launch_bounds__(256) void rgemm_kernel(
    const float* __restrict__ A, const float* __restrict__ Bm,
    float* __restrict__ C, float scl, float alpha)
{
    __shared__ float As[16][68], Bs[16][68];
    const int bm = blockIdx.y * 64, bn = blockIdx.x * 64;
    const int tid = threadIdx.x;
    const int tx = tid & 15, ty = tid >> 4;
    float acc[4][4] = {{0.f}};
    for (int k0 = 0; k0 < DIMSZ; k0 += 16) {
        #pragma unroll
        for (int i = 0; i < 4; i++) {
            int idx = tid + i * 256;
            int m = idx >> 4, kk = idx & 15;
            As[kk][m] = A[(size_t)(bm + m) * DIMSZ + k0 + kk];
            int n = idx & 63, k2 = idx >> 6;
            Bs[k2][n] = Bm[(size_t)(k0 + k2) * DIMSZ + bn + n];
        }
        __syncthreads();
        #pragma unroll
        for (int kk = 0; kk < 16; kk++) {
            float4 a4 = *(const float4*)&As[kk][ty * 4];
            float4 b4 = *(const float4*)&Bs[kk][tx * 4];
            float a[4] = {a4.x, a4.y, a4.z, a4.w};
            float b[4] = {b4.x, b4.y, b4.z, b4.w};
            #pragma unroll
            for (int i = 0; i < 4; i++)
                #pragma unroll
                for (int j = 0; j < 4; j++)
                    acc[i][j] += a[i] * b[j];
        }
        __syncthreads();
    }
    #pragma unroll
    for (int i = 0; i < 4; i++)
        #pragma unroll
        for (int j = 0; j < 4; j++) {
            int m = bm + ty * 4 + i, n = bn + tx * 4 + j;
            C[(size_t)m * DIMSZ + n] = scl * acc[i][j] + ((m == n) ? alpha : 0.f);
        }
}

// ---------------- FFT along seq axis ----------------
// mode 0: write fp32 (scaled). mode 1: write channel-paired 4 planes (Q/K).
// mode 2: write seq-paired 4 planes (V, transposed layout [b*DIMSZ+c][512]).
__global__ __launch_bounds__(256) void fft_kernel(float* __restrict__ re, float* __restrict__ im,
                                                  int inv, float scale,
                                                  uint32_t* __restrict__ pack, int mode)
{
    __shared__ float sr[SEQ * 4], si[SEQ * 4];
    __shared__ float twr[512], twi[512];
    const int c0 = blockIdx.x * 4;
    const int b = blockIdx.y;
    const size_t base = (size_t)b * SEQ * DIMSZ;
    const int tid = threadIdx.x;
    const float sgn = inv ? 1.0f : -1.0f;
    const size_t PS = (size_t)2048 * 512;

    #pragma unroll
    for (int j = tid; j < 512; j += 256) {
        float ang = 6.283185307179586f * (float)j * (1.0f / 1024.0f);
        float s, c;
        sincosf(ang, &s, &c);
        twr[j] = c; twi[j] = s;
    }

    for (int i = tid; i < SEQ * 4; i += 256) {
        int n = i >> 2, c = i & 3;
        int rn = __brev((unsigned)n) >> 22;
        size_t gg = base + (size_t)n * DIMSZ + c0 + c;
        sr[rn * 4 + c] = re[gg];
        si[rn * 4 + c] = im[gg];
    }
    __syncthreads();

    for (int s = 1; s <= 10; s++) {
        int half = 1 << (s - 1);
        int shift = 10 - s;
        for (int i = tid; i < 2048; i += 256) {
            int j = i >> 2, c = i & 3;
            int k = j & (half - 1);
            int grp = j >> (s - 1);
            int i0 = ((grp << s) + k) * 4 + c;
            int i1 = i0 + half * 4;
            int tw = k << shift;
            float cw = twr[tw];
            float sw = sgn * twi[tw];
            float ur = sr[i0], ui = si[i0];
            float vr = sr[i1], vi = si[i1];
            float tr = vr * cw - vi * sw;
            float ti = vr * sw + vi * cw;
            sr[i0] = ur + tr; si[i0] = ui + ti;
            sr[i1] = ur - tr; si[i1] = ui - ti;
        }
        __syncthreads();
    }

    if (mode == 0) {
        for (int i = tid; i < SEQ * 4; i += 256) {
            int n = i >> 2, c = i & 3;
            size_t gg = base + (size_t)n * DIMSZ + c0 + c;
            re[gg] = sr[n * 4 + c] * scale;
            im[gg] = si[n * 4 + c] * scale;
        }
    } else if (mode == 1) {
        for (int i = tid; i < 2048; i += 256) {
            int n = i >> 1, pp = i & 1;
            float f0 = sr[n * 4 + 2 * pp],     f1 = sr[n * 4 + 2 * pp + 1];
            float g0 = si[n * 4 + 2 * pp],     g1 = si[n * 4 + 2 * pp + 1];
            size_t idx = (size_t)(b * SEQ + n) * 512 + (c0 >> 1) + pp;
            uint32_t h, l;
            split2(f0, f1, h, l); pack[idx] = h; pack[PS + idx] = l;
            split2(g0, g1, h, l); pack[2 * PS + idx] = h; pack[3 * PS + idx] = l;
        }
    } else {
        for (int i = tid; i < 2048; i += 256) {
            int c = i & 3, p = i >> 2;
            float f0 = sr[(2 * p) * 4 + c], f1 = sr[(2 * p + 1) * 4 + c];
            float g0 = si[(2 * p) * 4 + c], g1 = si[(2 * p + 1) * 4 + c];
            size_t idx = (size_t)(b * DIMSZ + c0 + c) * 512 + p;
            uint32_t h, l;
            split2(f0, f1, h, l); pack[idx] = h; pack[PS + idx] = l;
            split2(g0, g1, h, l); pack[2 * PS + idx] = h; pack[3 * PS + idx] = l;
        }
    }
}

// ---------------- softmax over last dim (1024), writes packed hi/lo ----------------
__global__ __launch_bounds__(256) void softmax_kernel(const float* __restrict__ S,
                                                      uint32_t* __restrict__ Sp)
{
    const float* row = S + (size_t)blockIdx.x * SEQ;
    const int t = threadIdx.x;
    const size_t SPS = (size_t)32768 * 512;
    __shared__ float red[256];
    float4 v = *(const float4*)&row[t * 4];
    float m = fmaxf(fmaxf(v.x, v.y), fmaxf(v.z, v.w));
    red[t] = m; __syncthreads();
    for (int s = 128; s > 0; s >>= 1) {
        if (t < s) red[t] = fmaxf(red[t], red[t + s]);
        __syncthreads();
    }
    m = red[0]; __syncthreads();
    v.x = expf(v.x - m); v.y = expf(v.y - m);
    v.z = expf(v.z - m); v.w = expf(v.w - m);
    float sum = v.x + v.y + v.z + v.w;
    red[t] = sum; __syncthreads();
    for (int s = 128; s > 0; s >>= 1) {
        if (t < s) red[t] += red[t + s];
        __syncthreads();
    }
    float inv = 1.0f / red[0];
    v.x *= inv; v.y *= inv; v.z *= inv; v.w *= inv;
    size_t idx = (size_t)blockIdx.x * 512 + t * 2;
    uint32_t h, l;
    split2(v.x, v.y, h, l); Sp[idx] = h;     Sp[SPS + idx] = l;
    split2(v.z, v.w, h, l); Sp[idx + 1] = h; Sp[SPS + idx + 1] = l;
}

// ---------------- small elementwise kernels ----------------
__global__ __launch_bounds__(256) void scaleH_kernel(const float* __restrict__ H,
                                                     const float* __restrict__ dt,
                                                     float* __restrict__ M)
{
    int i = blockIdx.x * 256 + threadIdx.x;
    M[i] = H[i] * dt[0];
}

__global__ __launch_bounds__(256) void axpbI_kernel(const float* __restrict__ P,
                                                    float a, float b, float* __restrict__ T)
{
    int i = blockIdx.x * 256 + threadIdx.x;
    float v = a * P[i];
    int r = i >> 10, c = i & 1023;
    if (r == c) v += b;
    T[i] = v;
}

// ---------------- host launch ----------------
static void* symaddr(const void* sym)
{
    void* p = nullptr;
    cudaGetSymbolAddress(&p, sym);
    return p;
}

extern "C" void kernel_launch(void* const* d_in, const int* in_sizes, int n_in,
                              void* d_out, int out_size)
{
    const float* xr = (const float*)d_in[0];
    const float* xi = (const float*)d_in[1];
    const float* Wr_q = (const float*)d_in[2];  const float* Wi_q = (const float*)d_in[3];
    const float* br_q = (const float*)d_in[4];  const float* bi_q = (const float*)d_in[5];
    const float* Wr_k = (const float*)d_in[6];  const float* Wi_k = (const float*)d_in[7];
    const float* br_k = (const float*)d_in[8];  const float* bi_k = (const float*)d_in[9];
    const float* Wr_v = (const float*)d_in[10]; const float* Wi_v = (const float*)d_in[11];
    const float* br_v = (const float*)d_in[12]; const float* bi_v = (const float*)d_in[13];
    const float* Wr_o = (const float*)d_in[14]; const float* Wi_o = (const float*)d_in[15];
    const float* br_o = (const float*)d_in[16]; const float* bi_o = (const float*)d_in[17];
    const float* Wr_f1 = (const float*)d_in[18]; const float* Wi_f1 = (const float*)d_in[19];
    const float* br_f1 = (const float*)d_in[20]; const float* bi_f1 = (const float*)d_in[21];
    const float* Wr_f2 = (const float*)d_in[22]; const float* Wi_f2 = (const float*)d_in[23];
    const float* br_f2 = (const float*)d_in[24]; const float* bi_f2 = (const float*)d_in[25];
    const float* Hm = (const float*)d_in[26];
    const float* dt = (const float*)d_in[27];

    float* Qr = (float*)symaddr(g_Qr);   float* Qi = (float*)symaddr(g_Qi);
    float* Kr = (float*)symaddr(g_Kr);   float* Ki = (float*)symaddr(g_Ki);
    float* Vr = (float*)symaddr(g_Vr);   float* Vi = (float*)symaddr(g_Vi);
    float* Sb = (float*)symaddr(g_S);
    float* OFr = (float*)symaddr(g_OFr); float* OFi = (float*)symaddr(g_OFi);
    float* x1r = (float*)symaddr(g_x1r); float* x1i = (float*)symaddr(g_x1i);
    float* x2r = (float*)symaddr(g_x2r); float* x2i = (float*)symaddr(g_x2i);
    float* hr = (float*)symaddr(g_hr);   float* hi = (float*)symaddr(g_hi);
    float* Mx = (float*)symaddr(g_Mx);   float* P2 = (float*)symaddr(g_P2);
    float* T1 = (float*)symaddr(g_T1);   float* T2 = (float*)symaddr(g_T2);
    float* Uc = (float*)symaddr(g_Ucos); float* Us = (float*)symaddr(g_UsinN);

    uint32_t* pX  = (uint32_t*)symaddr(g_pX);
    uint32_t* pOF = (uint32_t*)symaddr(g_pOF);
    uint32_t* pX1 = (uint32_t*)symaddr(g_pX1);
    uint32_t* pX2 = (uint32_t*)symaddr(g_pX2);
    uint32_t* pH  = (uint32_t*)symaddr(g_pH);
    uint32_t* pWq = (uint32_t*)symaddr(g_pWq);
    uint32_t* pWk = (uint32_t*)symaddr(g_pWk);
    uint32_t* pWv = (uint32_t*)symaddr(g_pWv);
    uint32_t* pWo = (uint32_t*)symaddr(g_pWo);
    uint32_t* pF1 = (uint32_t*)symaddr(g_pF1);
    uint32_t* pF2 = (uint32_t*)symaddr(g_pF2);
    uint32_t* pU  = (uint32_t*)symaddr(g_pU);
    uint32_t* pQ  = (uint32_t*)symaddr(g_pQ);
    uint32_t* pK  = (uint32_t*)symaddr(g_pK);
    uint32_t* pV  = (uint32_t*)symaddr(g_pV);
    uint32_t* pS  = (uint32_t*)symaddr(g_pS);

    cudaFuncSetAttribute(cgemm_tc, cudaFuncAttributeMaxDynamicSharedMemorySize, CG_SMEM);
    cudaFuncSetAttribute(av_tc, cudaFuncAttributeMaxDynamicSharedMemorySize, AV_SMEM);

    dim3 blk(256);
    const size_t ACT  = (size_t)2048 * 512;   // activation pairs (M x 1024)
    const size_t ACTH = (size_t)2048 * 2048;  // h pairs (M x 4096)
    const size_t WDD  = (size_t)1024 * 512;   // D x D weight pairs
    const size_t WF1  = (size_t)4096 * 512;
    const size_t WF2  = (size_t)1024 * 2048;

    // --- pack weights + x ---
    pack6_kernel<<<WDD / 256, blk>>>(Wr_q, Wi_q, pWq, WDD);
    pack6_kernel<<<WDD / 256, blk>>>(Wr_k, Wi_k, pWk, WDD);
    pack6_kernel<<<WDD / 256, blk>>>(Wr_v, Wi_v, pWv, WDD);
    pack6_kernel<<<WDD / 256, blk>>>(Wr_o, Wi_o, pWo, WDD);
    pack6_kernel<<<WF1 / 256, blk>>>(Wr_f1, Wi_f1, pF1, WF1);
    pack6_kernel<<<WF2 / 256, blk>>>(Wr_f2, Wi_f2, pF2, WF2);
    pack6_kernel<<<ACT / 256, blk>>>(xr, xi, pX, ACT);

    dim3 gP(DIMSZ / 64, MROWS / 128);      // (16, 16)
    dim3 gF(DIMSZ / 4, BATCH);
    dim3 gS(SEQ / 64, SEQ / 128, BATCH * HEADS);
    dim3 gA(SEQ / 128, 1, BATCH * HEADS);
    dim3 gR(DIMSZ / 64, DIMSZ / 64);
    dim3 gF1(HIDDEN / 64, MROWS / 128);

    // --- QKV projections ---
    cgemm_tc<<<gP, blk, CG_SMEM>>>(pX, pWq, ACT, WDD, br_q, bi_q, nullptr, nullptr,
                                   Qr, Qi, DIMSZ, DIMSZ, 0);
    cgemm_tc<<<gP, blk, CG_SMEM>>>(pX, pWk, ACT, WDD, br_k, bi_k, nullptr, nullptr,
                                   Kr, Ki, DIMSZ, DIMSZ, 0);
    cgemm_tc<<<gP, blk, CG_SMEM>>>(pX, pWv, ACT, WDD, br_v, bi_v, nullptr, nullptr,
                                   Vr, Vi, DIMSZ, DIMSZ, 0);

    // --- FFTs (write packed planes for Q, K, V) ---
    fft_kernel<<<gF, blk>>>(Qr, Qi, 0, 1.0f, pQ, 1);
    fft_kernel<<<gF, blk>>>(Kr, Ki, 0, 1.0f, pK, 1);
    fft_kernel<<<gF, blk>>>(Vr, Vi, 0, 1.0f, pV, 2);

    // --- attention ---
    qk_tc<<<gS, blk>>>(pQ, pK, Sb);
    softmax_kernel<<<BATCH * HEADS * SEQ, blk>>>(Sb, pS);
    av_tc<<<gA, blk, AV_SMEM>>>(pS, pV, OFr, OFi);
    fft_kernel<<<gF, blk>>>(OFr, OFi, 1, 1.0f / (float)SEQ, nullptr, 0);

    // --- O projection + residual ---
    pack6_kernel<<<ACT / 256, blk>>>(OFr, OFi, pOF, ACT);
    cgemm_tc<<<gP, blk, CG_SMEM>>>(pOF, pWo, ACT, WDD, br_o, bi_o, xr, xi,
                                   x1r, x1i, DIMSZ, DIMSZ, 1);

    // --- FFN ---
    pack6_kernel<<<ACT / 256, blk>>>(x1r, x1i, pX1, ACT);
    cgemm_tc<<<gF1, blk, CG_SMEM>>>(pX1, pF1, ACT, WF1, br_f1, bi_f1, nullptr, nullptr,
                                    hr, hi, HIDDEN, DIMSZ, 2);
    pack6_kernel<<<ACTH / 256, blk>>>(hr, hi, pH, ACTH);
    cgemm_tc<<<gP, blk, CG_SMEM>>>(pH, pF2, ACTH, WF2, br_f2, bi_f2, x1r, x1i,
                                   x2r, x2i, DIMSZ, HIDDEN, 1);

    // --- U = expm(-i H dt) via Taylor/Horner in P2=(dtH)^2 ---
    scaleH_kernel<<<DIMSZ * DIMSZ / 256, blk>>>(Hm, dt, Mx);
    rgemm_kernel<<<gR, blk>>>(Mx, Mx, P2, 1.0f, 0.0f);
    axpbI_kernel<<<DIMSZ * DIMSZ / 256, blk>>>(P2, -1.0f / 720.0f, 1.0f / 24.0f, T1);
    rgemm_kernel<<<gR, blk>>>(T1, P2, T2, 1.0f, -0.5f);
    rgemm_kernel<<<gR, blk>>>(T2, P2, Uc, 1.0f, 1.0f);
    axpbI_kernel<<<DIMSZ * DIMSZ / 256, blk>>>(P2, -1.0f / 5040.0f, 1.0f / 120.0f, T1);
    rgemm_kernel<<<gR, blk>>>(T1, P2, T2, 1.0f, -1.0f / 6.0f);
    rgemm_kernel<<<gR, blk>>>(T2, P2, T1, 1.0f, 1.0f);
    rgemm_kernel<<<gR, blk>>>(Mx, T1, Us, -1.0f, 0.0f);   // Us = -sin(dtH)

    // --- final: out = x2 @ U (U symmetric) ---
    pack6_kernel<<<ACT / 256, blk>>>(x2r, x2i, pX2, ACT);
    pack6_kernel<<<WDD / 256, blk>>>(Uc, Us, pU, WDD);
    float* outR = (float*)d_out;
    float* outI = outR + (size_t)MROWS * DIMSZ;
    cgemm_tc<<<gP, blk, CG_SMEM>>>(pX2, pU, ACT, WDD, nullptr, nullptr, nullptr, nullptr,
                                   outR, outI, DIMSZ, DIMSZ, 0);
}